// round 1
// baseline (speedup 1.0000x reference)
#include <cuda_runtime.h>
#include <math.h>

#define NSTEPS 50
#define BATCH  131072
#define TPB    128
#define NBLK   (BATCH / TPB)   // 1024

static __device__ float g_part[NBLK];

typedef unsigned long long u64;

__device__ __forceinline__ u64 pack2(float a, float b) {
    u64 r;
    asm("mov.b64 %0, {%1, %2};"
        : "=l"(r) : "r"(__float_as_uint(a)), "r"(__float_as_uint(b)));
    return r;
}
__device__ __forceinline__ void unpack2(u64 p, float& a, float& b) {
    unsigned int x, y;
    asm("mov.b64 {%0, %1}, %2;" : "=r"(x), "=r"(y) : "l"(p));
    a = __uint_as_float(x); b = __uint_as_float(y);
}
// packed fp32x2 FMA (sm_100+): d = a*b + c elementwise on two packed floats
__device__ __forceinline__ u64 ffma2(u64 a, u64 b, u64 c) {
    u64 d;
    asm("fma.rn.f32x2 %0, %1, %2, %3;" : "=l"(d) : "l"(a), "l"(b), "l"(c));
    return d;
}

struct __align__(16) SmemW {
    float W1q[4 * 64];
    float W1z[4 * 64];
    float W2q[64 * 64];
    float W2z[64 * 64];
    float b1q[64], b1z[64], b2q[64], b2z[64];
    float W3q[64];        // qW3 is [64,1]
    float W3zT[3 * 64];   // zW3 [64,3] transposed -> [3][64]
    float b3q, b3z0, b3z1, b3z2;
};

// Shared trunk of both MLPs: x(4) -> relu(64) -> relu(64), all fp32 via packed f32x2 FMA.
// Weights read from SMEM with broadcast LDS.128 (uniform address across warp -> conflict-free).
__device__ __forceinline__ void mlp_trunk(const float* __restrict__ sW1,
                                          const float* __restrict__ sb1,
                                          const float* __restrict__ sW2,
                                          const float* __restrict__ sb2,
                                          const u64 xp[4],
                                          float h2[64]) {
    // ---- layer 1: [4] -> [64] ----
    u64 h1p[32];
    {
        const u64* b1p = (const u64*)sb1;
        #pragma unroll
        for (int j = 0; j < 32; j++) h1p[j] = b1p[j];
        #pragma unroll
        for (int r = 0; r < 4; r++) {
            const ulonglong2* wr = (const ulonglong2*)(sW1 + r * 64);
            u64 xr = xp[r];
            #pragma unroll
            for (int m = 0; m < 16; m++) {
                ulonglong2 w = wr[m];
                h1p[2 * m]     = ffma2(xr, w.x, h1p[2 * m]);
                h1p[2 * m + 1] = ffma2(xr, w.y, h1p[2 * m + 1]);
            }
        }
    }
    float h1[64];
    #pragma unroll
    for (int j = 0; j < 32; j++) {
        float a, b; unpack2(h1p[j], a, b);
        h1[2 * j]     = fmaxf(a, 0.0f);
        h1[2 * j + 1] = fmaxf(b, 0.0f);
    }

    // ---- layer 2: [64] -> [64] (dominant cost: 2048 FFMA2 + 1024 LDS.128) ----
    u64 h2p[32];
    {
        const u64* b2p = (const u64*)sb2;
        #pragma unroll
        for (int j = 0; j < 32; j++) h2p[j] = b2p[j];
        #pragma unroll 4
        for (int k = 0; k < 64; k++) {
            u64 a = pack2(h1[k], h1[k]);
            const ulonglong2* wr = (const ulonglong2*)(sW2 + k * 64);
            #pragma unroll
            for (int m = 0; m < 16; m++) {
                ulonglong2 w = wr[m];
                h2p[2 * m]     = ffma2(a, w.x, h2p[2 * m]);
                h2p[2 * m + 1] = ffma2(a, w.y, h2p[2 * m + 1]);
            }
        }
    }
    #pragma unroll
    for (int j = 0; j < 32; j++) {
        float a, b; unpack2(h2p[j], a, b);
        h2[2 * j]     = fmaxf(a, 0.0f);
        h2[2 * j + 1] = fmaxf(b, 0.0f);
    }
}

__global__ void __launch_bounds__(TPB)
bsde_kernel(const float* __restrict__ y0v, const float* __restrict__ Y0v,
            const float* __restrict__ qW1, const float* __restrict__ qb1,
            const float* __restrict__ qW2, const float* __restrict__ qb2,
            const float* __restrict__ qW3, const float* __restrict__ qb3,
            const float* __restrict__ zW1, const float* __restrict__ zb1,
            const float* __restrict__ zW2, const float* __restrict__ zb2,
            const float* __restrict__ zW3, const float* __restrict__ zb3,
            const float* __restrict__ dW) {
    __shared__ SmemW S;
    const int tid = threadIdx.x;

    // Cooperative weight staging into SMEM (tiny vs total work)
    for (int i = tid; i < 4 * 64; i += TPB) { S.W1q[i] = qW1[i]; S.W1z[i] = zW1[i]; }
    for (int i = tid; i < 64 * 64; i += TPB) { S.W2q[i] = qW2[i]; S.W2z[i] = zW2[i]; }
    for (int i = tid; i < 64; i += TPB) {
        S.b1q[i] = qb1[i]; S.b1z[i] = zb1[i];
        S.b2q[i] = qb2[i]; S.b2z[i] = zb2[i];
        S.W3q[i] = qW3[i];
        S.W3zT[0 * 64 + i] = zW3[i * 3 + 0];
        S.W3zT[1 * 64 + i] = zW3[i * 3 + 1];
        S.W3zT[2 * 64 + i] = zW3[i * 3 + 2];
    }
    if (tid == 0) { S.b3q = qb3[0]; S.b3z0 = zb3[0]; S.b3z1 = zb3[1]; S.b3z2 = zb3[2]; }
    __syncthreads();

    const int elem = blockIdx.x * TPB + tid;
    const float dt = 0.02f;
    const float sqdt = sqrtf(dt);

    float y0 = y0v[0], y1 = y0v[1], y2 = y0v[2];
    float Y  = Y0v[0];

    for (int n = 0; n < NSTEPS; n++) {
        const float* dwp = dW + ((size_t)n * BATCH + elem) * 3;
        float dw0 = dwp[0] * sqdt;
        float dw1 = dwp[1] * sqdt;
        float dw2 = dwp[2] * sqdt;
        float t = (float)n * dt;

        u64 xp[4];
        xp[0] = pack2(t,  t);
        xp[1] = pack2(y0, y0);
        xp[2] = pack2(y1, y1);
        xp[3] = pack2(y2, y2);

        float h2[64];

        // ---- z MLP ----
        mlp_trunk(S.W1z, S.b1z, S.W2z, S.b2z, xp, h2);
        float z0 = S.b3z0, z1 = S.b3z1, z2 = S.b3z2;
        {
            const float4* w0 = (const float4*)&S.W3zT[0];
            const float4* w1 = (const float4*)&S.W3zT[64];
            const float4* w2 = (const float4*)&S.W3zT[128];
            #pragma unroll
            for (int m = 0; m < 16; m++) {
                float4 a = w0[m], b = w1[m], c = w2[m];
                float h0 = h2[4 * m], hA = h2[4 * m + 1], hB = h2[4 * m + 2], hC = h2[4 * m + 3];
                z0 += h0 * a.x + hA * a.y + hB * a.z + hC * a.w;
                z1 += h0 * b.x + hA * b.y + hB * b.z + hC * b.w;
                z2 += h0 * c.x + hA * c.y + hB * c.z + hC * c.w;
            }
        }

        // ---- q MLP ----
        mlp_trunk(S.W1q, S.b1q, S.W2q, S.b2q, xp, h2);
        float q = S.b3q;
        {
            const float4* wq = (const float4*)&S.W3q[0];
            #pragma unroll
            for (int m = 0; m < 16; m++) {
                float4 a = wq[m];
                q += h2[4 * m] * a.x + h2[4 * m + 1] * a.y
                   + h2[4 * m + 2] * a.z + h2[4 * m + 3] * a.w;
            }
        }

        // ---- SDE update (uses OLD y for drift & sigma) ----
        float f  = 0.5f * q * q;
        float s0 = 0.2f + 0.1f * tanhf(y0);
        float s1 = 0.2f + 0.1f * tanhf(y1);
        float s2 = 0.2f + 0.1f * tanhf(y2);
        y0 += (q - y0) * dt + s0 * dw0;
        y1 += (q - y1) * dt + s1 * dw1;
        y2 += (q - y2) * dt + s2 * dw2;
        Y  += -f * dt + z0 * dw0 + z1 * dw1 + z2 * dw2;
    }

    // per-path loss term
    float term = y0 * y0 + y1 * y1 + y2 * y2;
    float v = Y - term;
    v = v * v;

    // deterministic block reduction
    #pragma unroll
    for (int off = 16; off > 0; off >>= 1)
        v += __shfl_down_sync(0xffffffffu, v, off);
    __shared__ float red[TPB / 32];
    if ((tid & 31) == 0) red[tid >> 5] = v;
    __syncthreads();
    if (tid == 0) {
        float s = 0.0f;
        #pragma unroll
        for (int w = 0; w < TPB / 32; w++) s += red[w];
        g_part[blockIdx.x] = s;
    }
}

__global__ void __launch_bounds__(256)
reduce_kernel(float* __restrict__ out) {
    __shared__ float s[256];
    const int t = threadIdx.x;
    float v = 0.0f;
    for (int i = t; i < NBLK; i += 256) v += g_part[i];
    s[t] = v;
    __syncthreads();
    for (int k = 128; k > 0; k >>= 1) {
        if (t < k) s[t] += s[t + k];
        __syncthreads();
    }
    if (t == 0) out[0] = s[0] * (1.0f / (float)BATCH);
}

extern "C" void kernel_launch(void* const* d_in, const int* in_sizes, int n_in,
                              void* d_out, int out_size) {
    const float* y0  = (const float*)d_in[0];
    const float* Y0  = (const float*)d_in[1];
    const float* qW1 = (const float*)d_in[2];
    const float* qb1 = (const float*)d_in[3];
    const float* qW2 = (const float*)d_in[4];
    const float* qb2 = (const float*)d_in[5];
    const float* qW3 = (const float*)d_in[6];
    const float* qb3 = (const float*)d_in[7];
    const float* zW1 = (const float*)d_in[8];
    const float* zb1 = (const float*)d_in[9];
    const float* zW2 = (const float*)d_in[10];
    const float* zb2 = (const float*)d_in[11];
    const float* zW3 = (const float*)d_in[12];
    const float* zb3 = (const float*)d_in[13];
    const float* dW  = (const float*)d_in[14];

    bsde_kernel<<<NBLK, TPB>>>(y0, Y0, qW1, qb1, qW2, qb2, qW3, qb3,
                               zW1, zb1, zW2, zb2, zW3, zb3, dW);
    reduce_kernel<<<1, 256>>>((float*)d_out);
}

// round 2
// speedup vs baseline: 2.9081x; 2.9081x over previous
#include <cuda_runtime.h>
#include <math.h>

#define NSTEPS 50
#define BATCH  131072
#define TPB    256
#define PATHS  256                 // paths per CTA (== TPB)
#define NBLK   (BATCH / PATHS)     // 512

static __device__ float g_part[NBLK];

typedef unsigned long long u64;

__device__ __forceinline__ u64 pack2(float a, float b) {
    u64 r;
    asm("mov.b64 %0, {%1, %2};"
        : "=l"(r) : "r"(__float_as_uint(a)), "r"(__float_as_uint(b)));
    return r;
}
__device__ __forceinline__ void unpack2(u64 p, float& a, float& b) {
    unsigned int x, y;
    asm("mov.b64 {%0, %1}, %2;" : "=r"(x), "=r"(y) : "l"(p));
    a = __uint_as_float(x); b = __uint_as_float(y);
}
__device__ __forceinline__ u64 ffma2(u64 a, u64 b, u64 c) {
    u64 d;
    asm("fma.rn.f32x2 %0, %1, %2, %3;" : "=l"(d) : "l"(a), "l"(b), "l"(c));
    return d;
}

// ---- dynamic smem layout (floats) ----
// W2z: [0,4096)  W2q: [4096,8192)  W1z: [8192,8448)  W1q: [8448,8704)
// b1z: 8704  b1q: 8768  b2z: 8832  b2q: 8896
// W3zT: [8960,9152)  W3q: [9152,9216)  b3s: [9216,9220)
// sH (H1T[64][256], also aliased for partials): [9232, 25616)
// sX (XT[4][256]): [25616, 26640)
#define SM_FLOATS 26640
#define SMEM_BYTES (SM_FLOATS * 4)

// Cooperative trunk: x[4] -> relu(64) -> relu(64); leaves layer-2 pre-relu
// accumulators (4 paths x 8 neuron-pairs) in acc[][].
__device__ __forceinline__ void trunk_tiled(const float* __restrict__ sW1,
                                            const float* __restrict__ sb1,
                                            const float* __restrict__ sW2,
                                            const float* __restrict__ sb2,
                                            const float* __restrict__ sX,
                                            float* __restrict__ sH,
                                            int pg, int ng,
                                            u64 acc[4][8]) {
    // ---- layer 1: [4] -> [64] ----
    {
        const u64* bb = (const u64*)(sb1 + 16 * ng);
        u64 b[8];
        #pragma unroll
        for (int j = 0; j < 8; j++) b[j] = bb[j];
        #pragma unroll
        for (int pi = 0; pi < 4; pi++)
            #pragma unroll
            for (int j = 0; j < 8; j++) acc[pi][j] = b[j];

        #pragma unroll
        for (int k = 0; k < 4; k++) {
            float4 xv = *(const float4*)(sX + k * PATHS + 4 * pg);
            const ulonglong2* wr = (const ulonglong2*)(sW1 + k * 64 + 16 * ng);
            ulonglong2 wA = wr[0], wB = wr[1], wC = wr[2], wD = wr[3];
            u64 w[8] = {wA.x, wA.y, wB.x, wB.y, wC.x, wC.y, wD.x, wD.y};
            float xs[4] = {xv.x, xv.y, xv.z, xv.w};
            #pragma unroll
            for (int pi = 0; pi < 4; pi++) {
                u64 a = pack2(xs[pi], xs[pi]);
                #pragma unroll
                for (int j = 0; j < 8; j++) acc[pi][j] = ffma2(a, w[j], acc[pi][j]);
            }
        }
    }
    // relu -> sH (transposed: neuron-major, path-minor)
    #pragma unroll
    for (int j = 0; j < 8; j++) {
        int n0 = 16 * ng + 2 * j;
        float a0, b0, a1, b1, a2, b2, a3, b3;
        unpack2(acc[0][j], a0, b0);
        unpack2(acc[1][j], a1, b1);
        unpack2(acc[2][j], a2, b2);
        unpack2(acc[3][j], a3, b3);
        float4 v0 = {fmaxf(a0, 0.f), fmaxf(a1, 0.f), fmaxf(a2, 0.f), fmaxf(a3, 0.f)};
        float4 v1 = {fmaxf(b0, 0.f), fmaxf(b1, 0.f), fmaxf(b2, 0.f), fmaxf(b3, 0.f)};
        *(float4*)(sH + n0 * PATHS + 4 * pg)       = v0;
        *(float4*)(sH + (n0 + 1) * PATHS + 4 * pg) = v1;
    }
    __syncthreads();   // H1 ready

    // ---- layer 2: [64] -> [64] ----
    {
        const u64* bb = (const u64*)(sb2 + 16 * ng);
        u64 b[8];
        #pragma unroll
        for (int j = 0; j < 8; j++) b[j] = bb[j];
        #pragma unroll
        for (int pi = 0; pi < 4; pi++)
            #pragma unroll
            for (int j = 0; j < 8; j++) acc[pi][j] = b[j];

        #pragma unroll 8
        for (int k = 0; k < 64; k++) {
            float4 hv = *(const float4*)(sH + k * PATHS + 4 * pg);
            const ulonglong2* wr = (const ulonglong2*)(sW2 + k * 64 + 16 * ng);
            ulonglong2 wA = wr[0], wB = wr[1], wC = wr[2], wD = wr[3];
            u64 w[8] = {wA.x, wA.y, wB.x, wB.y, wC.x, wC.y, wD.x, wD.y};
            float hs[4] = {hv.x, hv.y, hv.z, hv.w};
            #pragma unroll
            for (int pi = 0; pi < 4; pi++) {
                u64 a = pack2(hs[pi], hs[pi]);
                #pragma unroll
                for (int j = 0; j < 8; j++) acc[pi][j] = ffma2(a, w[j], acc[pi][j]);
            }
        }
    }
    __syncthreads();   // all H reads done -> partial region (aliased on sH) is writable
}

__global__ void __launch_bounds__(TPB)
bsde_kernel(const float* __restrict__ y0v, const float* __restrict__ Y0v,
            const float* __restrict__ qW1, const float* __restrict__ qb1,
            const float* __restrict__ qW2, const float* __restrict__ qb2,
            const float* __restrict__ qW3, const float* __restrict__ qb3,
            const float* __restrict__ zW1, const float* __restrict__ zb1,
            const float* __restrict__ zW2, const float* __restrict__ zb2,
            const float* __restrict__ zW3, const float* __restrict__ zb3,
            const float* __restrict__ dW) {
    extern __shared__ float smem[];
    float* W2z = smem;
    float* W2q = smem + 4096;
    float* W1z = smem + 8192;
    float* W1q = smem + 8448;
    float* b1z = smem + 8704;
    float* b1q = smem + 8768;
    float* b2z = smem + 8832;
    float* b2q = smem + 8896;
    float* W3zT = smem + 8960;   // [3][64]
    float* W3q  = smem + 9152;
    float* b3s  = smem + 9216;   // {qb3, zb3_0, zb3_1, zb3_2}
    float* sH   = smem + 9232;   // H1T[64][256]; partials aliased at base
    float* sX   = smem + 25616;  // XT[4][256]

    float* Pz0 = sH;             // [4][256] each
    float* Pz1 = sH + 1024;
    float* Pz2 = sH + 2048;
    float* Pq  = sH + 3072;

    const int tid = threadIdx.x;

    // ---- stage weights ----
    for (int i = tid; i < 4096; i += TPB) { W2z[i] = zW2[i]; W2q[i] = qW2[i]; }
    for (int i = tid; i < 256;  i += TPB) { W1z[i] = zW1[i]; W1q[i] = qW1[i]; }
    if (tid < 64) {
        b1z[tid] = zb1[tid]; b1q[tid] = qb1[tid];
        b2z[tid] = zb2[tid]; b2q[tid] = qb2[tid];
        W3q[tid] = qW3[tid];
        W3zT[tid]       = zW3[tid * 3 + 0];
        W3zT[64 + tid]  = zW3[tid * 3 + 1];
        W3zT[128 + tid] = zW3[tid * 3 + 2];
    }
    if (tid == 0) { b3s[0] = qb3[0]; b3s[1] = zb3[0]; b3s[2] = zb3[1]; b3s[3] = zb3[2]; }

    const int pg = tid & 63;    // path group: paths 4*pg .. 4*pg+3
    const int ng = tid >> 6;    // neuron group: neurons 16*ng .. 16*ng+15
    const int gp = blockIdx.x * PATHS + tid;   // this thread's owned path

    const float dt = 0.02f;
    const float sqdt = sqrtf(dt);
    float y0 = y0v[0], y1 = y0v[1], y2 = y0v[2];
    float Y  = Y0v[0];

    u64 acc[4][8];

    for (int n = 0; n < NSTEPS; n++) {
        float t = (float)n * dt;
        // stage X transposed (tid == path)
        sX[0 * PATHS + tid] = t;
        sX[1 * PATHS + tid] = y0;
        sX[2 * PATHS + tid] = y1;
        sX[3 * PATHS + tid] = y2;
        __syncthreads();   // X ready; also orders prev-step Pq reads before H1T reuse

        // ================= z MLP =================
        trunk_tiled(W1z, b1z, W2z, b2z, sX, sH, pg, ng, acc);
        {
            float p0[4] = {0, 0, 0, 0}, p1[4] = {0, 0, 0, 0}, p2[4] = {0, 0, 0, 0};
            #pragma unroll
            for (int j = 0; j < 8; j++) {
                int n0 = 16 * ng + 2 * j;
                float w00 = W3zT[n0],       w01 = W3zT[n0 + 1];
                float w10 = W3zT[64 + n0],  w11 = W3zT[64 + n0 + 1];
                float w20 = W3zT[128 + n0], w21 = W3zT[128 + n0 + 1];
                #pragma unroll
                for (int pi = 0; pi < 4; pi++) {
                    float h0, h1; unpack2(acc[pi][j], h0, h1);
                    h0 = fmaxf(h0, 0.f); h1 = fmaxf(h1, 0.f);
                    p0[pi] += h0 * w00 + h1 * w01;
                    p1[pi] += h0 * w10 + h1 * w11;
                    p2[pi] += h0 * w20 + h1 * w21;
                }
            }
            #pragma unroll
            for (int pi = 0; pi < 4; pi++) {
                int p = 4 * pg + pi;
                Pz0[ng * PATHS + p] = p0[pi];
                Pz1[ng * PATHS + p] = p1[pi];
                Pz2[ng * PATHS + p] = p2[pi];
            }
        }
        __syncthreads();   // partials ready
        float z0 = b3s[1] + Pz0[tid] + Pz0[PATHS + tid] + Pz0[2 * PATHS + tid] + Pz0[3 * PATHS + tid];
        float z1 = b3s[2] + Pz1[tid] + Pz1[PATHS + tid] + Pz1[2 * PATHS + tid] + Pz1[3 * PATHS + tid];
        float z2 = b3s[3] + Pz2[tid] + Pz2[PATHS + tid] + Pz2[2 * PATHS + tid] + Pz2[3 * PATHS + tid];
        __syncthreads();   // partial reads done -> H1T writable for q MLP

        // ================= q MLP =================
        trunk_tiled(W1q, b1q, W2q, b2q, sX, sH, pg, ng, acc);
        {
            float p0[4] = {0, 0, 0, 0};
            #pragma unroll
            for (int j = 0; j < 8; j++) {
                int n0 = 16 * ng + 2 * j;
                float w0 = W3q[n0], w1 = W3q[n0 + 1];
                #pragma unroll
                for (int pi = 0; pi < 4; pi++) {
                    float h0, h1; unpack2(acc[pi][j], h0, h1);
                    p0[pi] += fmaxf(h0, 0.f) * w0 + fmaxf(h1, 0.f) * w1;
                }
            }
            #pragma unroll
            for (int pi = 0; pi < 4; pi++)
                Pq[ng * PATHS + 4 * pg + pi] = p0[pi];
        }
        __syncthreads();   // q partials ready
        float q = b3s[0] + Pq[tid] + Pq[PATHS + tid] + Pq[2 * PATHS + tid] + Pq[3 * PATHS + tid];
        // (next-iteration top sync orders Pq reads before H1T reuse)

        // ================= SDE update (per owned path) =================
        const float* dwp = dW + ((size_t)n * BATCH + gp) * 3;
        float dw0 = dwp[0] * sqdt;
        float dw1 = dwp[1] * sqdt;
        float dw2 = dwp[2] * sqdt;

        float f  = 0.5f * q * q;
        float s0 = 0.2f + 0.1f * tanhf(y0);
        float s1 = 0.2f + 0.1f * tanhf(y1);
        float s2 = 0.2f + 0.1f * tanhf(y2);
        y0 += (q - y0) * dt + s0 * dw0;
        y1 += (q - y1) * dt + s1 * dw1;
        y2 += (q - y2) * dt + s2 * dw2;
        Y  += -f * dt + z0 * dw0 + z1 * dw1 + z2 * dw2;
    }

    // per-path loss, deterministic block reduction
    float term = y0 * y0 + y1 * y1 + y2 * y2;
    float v = Y - term;
    v = v * v;
    #pragma unroll
    for (int off = 16; off > 0; off >>= 1)
        v += __shfl_down_sync(0xffffffffu, v, off);
    __shared__ float red[TPB / 32];
    if ((tid & 31) == 0) red[tid >> 5] = v;
    __syncthreads();
    if (tid == 0) {
        float s = 0.0f;
        #pragma unroll
        for (int w = 0; w < TPB / 32; w++) s += red[w];
        g_part[blockIdx.x] = s;
    }
}

__global__ void __launch_bounds__(256)
reduce_kernel(float* __restrict__ out) {
    __shared__ float s[256];
    const int t = threadIdx.x;
    float v = 0.0f;
    for (int i = t; i < NBLK; i += 256) v += g_part[i];
    s[t] = v;
    __syncthreads();
    for (int k = 128; k > 0; k >>= 1) {
        if (t < k) s[t] += s[t + k];
        __syncthreads();
    }
    if (t == 0) out[0] = s[0] * (1.0f / (float)BATCH);
}

// padding launches so ncu's "-s 5" (index 5 mod 4 == 1) lands on bsde_kernel
__global__ void pad_kernel() {}

extern "C" void kernel_launch(void* const* d_in, const int* in_sizes, int n_in,
                              void* d_out, int out_size) {
    const float* y0  = (const float*)d_in[0];
    const float* Y0  = (const float*)d_in[1];
    const float* qW1 = (const float*)d_in[2];
    const float* qb1 = (const float*)d_in[3];
    const float* qW2 = (const float*)d_in[4];
    const float* qb2 = (const float*)d_in[5];
    const float* qW3 = (const float*)d_in[6];
    const float* qb3 = (const float*)d_in[7];
    const float* zW1 = (const float*)d_in[8];
    const float* zb1 = (const float*)d_in[9];
    const float* zW2 = (const float*)d_in[10];
    const float* zb2 = (const float*)d_in[11];
    const float* zW3 = (const float*)d_in[12];
    const float* zb3 = (const float*)d_in[13];
    const float* dW  = (const float*)d_in[14];

    static int attr_done = 0;
    if (!attr_done) {
        cudaFuncSetAttribute(bsde_kernel,
                             cudaFuncAttributeMaxDynamicSharedMemorySize, SMEM_BYTES);
        attr_done = 1;
    }

    pad_kernel<<<1, 32>>>();                       // launch 0 (pad)
    bsde_kernel<<<NBLK, TPB, SMEM_BYTES>>>(        // launch 1 (profiled by -s 5)
        y0, Y0, qW1, qb1, qW2, qb2, qW3, qb3,
        zW1, zb1, zW2, zb2, zW3, zb3, dW);
    pad_kernel<<<1, 32>>>();                       // launch 2 (pad)
    reduce_kernel<<<1, 256>>>((float*)d_out);      // launch 3
}

// round 7
// speedup vs baseline: 5.3614x; 1.8436x over previous
#include <cuda_runtime.h>
#include <cuda_bf16.h>
#include <math.h>
#include <stdint.h>

#define NSTEPS 50
#define BATCH  131072
#define TPB    128
#define NBLK   (BATCH / TPB)   // 1024

static __device__ float g_part[NBLK];
static __device__ int   g_cnt = 0;

typedef unsigned long long u64;
typedef unsigned int u32;

// ---------------- helpers ----------------
__device__ __forceinline__ u32 smem_u32(const void* p) {
    u32 a;
    asm("{ .reg .u64 t; cvta.to.shared.u64 t, %1; cvt.u32.u64 %0, t; }" : "=r"(a) : "l"(p));
    return a;
}
__device__ __forceinline__ u64 pack2(float a, float b) {
    u64 r; asm("mov.b64 %0, {%1, %2};" : "=l"(r) : "r"(__float_as_uint(a)), "r"(__float_as_uint(b))); return r;
}
__device__ __forceinline__ void unpack2(u64 p, float& a, float& b) {
    u32 x, y; asm("mov.b64 {%0, %1}, %2;" : "=r"(x), "=r"(y) : "l"(p));
    a = __uint_as_float(x); b = __uint_as_float(y);
}
__device__ __forceinline__ u64 ffma2(u64 a, u64 b, u64 c) {
    u64 d; asm("fma.rn.f32x2 %0, %1, %2, %3;" : "=l"(d) : "l"(a), "l"(b), "l"(c)); return d;
}
// packed bf16x2: lo -> low 16 bits, hi -> high 16 bits
__device__ __forceinline__ u32 cvt_bf16x2(float lo, float hi) {
    u32 r; asm("cvt.rn.bf16x2.f32 %0, %1, %2;" : "=r"(r) : "f"(hi), "f"(lo)); return r;
}

__device__ __forceinline__ void mma16816(float c[4], const u32 a[4], const u32 b[2]) {
    asm volatile("mma.sync.aligned.m16n8k16.row.col.f32.bf16.bf16.f32 "
                 "{%0,%1,%2,%3}, {%4,%5,%6,%7}, {%8,%9}, {%0,%1,%2,%3};"
                 : "+f"(c[0]), "+f"(c[1]), "+f"(c[2]), "+f"(c[3])
                 : "r"(a[0]), "r"(a[1]), "r"(a[2]), "r"(a[3]), "r"(b[0]), "r"(b[1]));
}
__device__ __forceinline__ void ldsm4(u32 r[4], u32 addr) {
    asm volatile("ldmatrix.sync.aligned.m8n8.x4.shared.b16 {%0,%1,%2,%3}, [%4];"
                 : "=r"(r[0]), "=r"(r[1]), "=r"(r[2]), "=r"(r[3]) : "r"(addr));
}

// ---- dynamic smem layout (bytes) ----
// A buffers: [128 rows][64 bf16] = 128B/row, XOR-swizzled 16B chunks
#define A_ZH 0
#define A_ZL 16384
#define A_QH 32768
#define A_QL 49152
#define P_Z0 65536            // [128][4] f32
#define P_Z1 (P_Z0 + 2048)
#define P_Z2 (P_Z0 + 4096)
#define P_Q  (P_Z0 + 6144)
#define W1_Z (P_Z0 + 8192)    // 256 floats
#define W1_Q (W1_Z + 1024)    // 256 floats
#define B1_Z (W1_Q + 1024)    // 64 floats
#define B1_Q (B1_Z + 256)     // 64 floats
#define SMEM_BYTES (B1_Q + 256)   // 76032 B

// layer 1 (fp32, packed f32x2) -> relu -> bf16 hi/lo -> swizzled SMEM row (row = tid)
__device__ __forceinline__ void layer1_store(const float* __restrict__ sW1,
                                             const float* __restrict__ sb1,
                                             float xt, float y0, float y1, float y2,
                                             char* smemc, int offH, int offL, int tid) {
    u64 acc[32];
    const u64* bp = (const u64*)sb1;
    #pragma unroll
    for (int j = 0; j < 32; j++) acc[j] = bp[j];
    float xs[4] = {xt, y0, y1, y2};
    #pragma unroll
    for (int r = 0; r < 4; r++) {
        u64 xr = pack2(xs[r], xs[r]);
        const u64* wr = (const u64*)(sW1 + r * 64);
        #pragma unroll
        for (int j = 0; j < 32; j++) acc[j] = ffma2(xr, wr[j], acc[j]);
    }
    u32 hi[32], lo[32];
    #pragma unroll
    for (int j = 0; j < 32; j++) {
        float a, b; unpack2(acc[j], a, b);
        a = fmaxf(a, 0.0f); b = fmaxf(b, 0.0f);
        u32 hp = cvt_bf16x2(a, b);
        float ha = __uint_as_float(hp << 16);
        float hb = __uint_as_float(hp & 0xFFFF0000u);
        hi[j] = hp;
        lo[j] = cvt_bf16x2(a - ha, b - hb);
    }
    const int r7 = tid & 7;
    char* rowH = smemc + offH + tid * 128;
    char* rowL = smemc + offL + tid * 128;
    #pragma unroll
    for (int c = 0; c < 8; c++) {
        int o = ((c ^ r7) << 4);
        *(uint4*)(rowH + o) = make_uint4(hi[4*c], hi[4*c+1], hi[4*c+2], hi[4*c+3]);
        *(uint4*)(rowL + o) = make_uint4(lo[4*c], lo[4*c+1], lo[4*c+2], lo[4*c+3]);
    }
}

__global__ void __launch_bounds__(TPB)
bsde_kernel(const float* __restrict__ y0v, const float* __restrict__ Y0v,
            const float* __restrict__ qW1, const float* __restrict__ qb1,
            const float* __restrict__ qW2, const float* __restrict__ qb2,
            const float* __restrict__ qW3, const float* __restrict__ qb3,
            const float* __restrict__ zW1, const float* __restrict__ zb1,
            const float* __restrict__ zW2, const float* __restrict__ zb2,
            const float* __restrict__ zW3, const float* __restrict__ zb3,
            const float* __restrict__ dW, float* __restrict__ out) {
    extern __shared__ char smemc[];
    __shared__ float s_red[4];
    __shared__ int s_last;

    const int tid  = threadIdx.x;
    const int lane = tid & 31;
    const int wid  = tid >> 5;
    const int g    = lane >> 2;   // group id (row within tile)
    const int tg   = lane & 3;    // thread-in-group (col pair)
    const u32 sb   = smem_u32(smemc);

    // ---- stage W1/b1 in SMEM ----
    float* sW1z = (float*)(smemc + W1_Z);
    float* sW1q = (float*)(smemc + W1_Q);
    float* sb1z = (float*)(smemc + B1_Z);
    float* sb1q = (float*)(smemc + B1_Q);
    for (int i = tid; i < 256; i += TPB) { sW1z[i] = zW1[i]; sW1q[i] = qW1[i]; }
    if (tid < 64) { sb1z[tid] = zb1[tid]; sb1q[tid] = qb1[tid]; }

    // ---- per-thread layer-3 / bias preloads (4 owned columns) ----
    const int col0 = wid * 16 + tg * 2;     // cols: col0, col0+1, col0+8, col0+9
    float b2zc[4], b2qc[4], wz0[4], wz1[4], wz2[4], wqc[4];
    #pragma unroll
    for (int i = 0; i < 4; i++) {
        int c = col0 + (i >> 1) * 8 + (i & 1);
        b2zc[i] = zb2[c]; b2qc[i] = qb2[c];
        wz0[i] = zW3[c * 3 + 0]; wz1[i] = zW3[c * 3 + 1]; wz2[i] = zW3[c * 3 + 2];
        wqc[i] = qW3[c];
    }

    // ---- B fragments (W2), resident in registers for the whole run ----
    // idx = nt*8 + kt*2 + r ; element pair (k0, k0+1), k0 = kt*16 + tg*2 + r*8, n = wid*16 + nt*8 + g
    u32 Bzh[16], Bzl[16], Bqh[16], Bql[16];
    #pragma unroll
    for (int nt = 0; nt < 2; nt++) {
        int nn = wid * 16 + nt * 8 + g;
        #pragma unroll
        for (int kt = 0; kt < 4; kt++) {
            #pragma unroll
            for (int r = 0; r < 2; r++) {
                int k0 = kt * 16 + tg * 2 + r * 8;
                int idx = nt * 8 + kt * 2 + r;
                float a = zW2[k0 * 64 + nn], b = zW2[(k0 + 1) * 64 + nn];
                u32 hp = cvt_bf16x2(a, b);
                Bzh[idx] = hp;
                Bzl[idx] = cvt_bf16x2(a - __uint_as_float(hp << 16),
                                      b - __uint_as_float(hp & 0xFFFF0000u));
                a = qW2[k0 * 64 + nn]; b = qW2[(k0 + 1) * 64 + nn];
                hp = cvt_bf16x2(a, b);
                Bqh[idx] = hp;
                Bql[idx] = cvt_bf16x2(a - __uint_as_float(hp << 16),
                                      b - __uint_as_float(hp & 0xFFFF0000u));
            }
        }
    }

    // ---- ldmatrix per-lane offsets (row-swizzled) ----
    const int mat = lane >> 3, r8 = lane & 7;
    const int rowLocal = (mat & 1) * 8 + r8;   // row within 16-row m-tile
    u32 offk[4];
    #pragma unroll
    for (int k = 0; k < 4; k++)
        offk[k] = (u32)(rowLocal * 128 + ((((k << 1) + (mat >> 1)) ^ r8) << 4));

    const float zb3_0 = zb3[0], zb3_1 = zb3[1], zb3_2 = zb3[2], qb3_0 = qb3[0];
    const int gp = blockIdx.x * TPB + tid;
    const float dt = 0.02f;
    const float sqdt = sqrtf(dt);
    float y0 = y0v[0], y1 = y0v[1], y2 = y0v[2];
    float Y  = Y0v[0];
    __syncthreads();

    for (int n = 0; n < NSTEPS; n++) {
        const float* dwp = dW + ((size_t)n * BATCH + gp) * 3;
        float dw0 = dwp[0] * sqdt;
        float dw1 = dwp[1] * sqdt;
        float dw2 = dwp[2] * sqdt;
        float t = (float)n * dt;

        // ---- layer 1 for both MLPs, write A operands ----
        layer1_store(sW1z, sb1z, t, y0, y1, y2, smemc, A_ZH, A_ZL, tid);
        layer1_store(sW1q, sb1q, t, y0, y1, y2, smemc, A_QH, A_QL, tid);
        __syncthreads();

        // ---- z trunk: layer 2 GEMM (split bf16) + fused layer-3 partials ----
        #pragma unroll 1
        for (int m = 0; m < 8; m++) {
            u32 Ah[16], Al[16];
            #pragma unroll
            for (int k = 0; k < 4; k++) {
                ldsm4(&Ah[4 * k], sb + A_ZH + m * 2048 + offk[k]);
                ldsm4(&Al[4 * k], sb + A_ZL + m * 2048 + offk[k]);
            }
            float cA[4] = {0, 0, 0, 0}, cB[4] = {0, 0, 0, 0};
            #pragma unroll
            for (int k = 0; k < 4; k++) {
                mma16816(cA, &Ah[4 * k], &Bzh[k * 2]);
                mma16816(cA, &Ah[4 * k], &Bzl[k * 2]);
                mma16816(cA, &Al[4 * k], &Bzh[k * 2]);
                mma16816(cB, &Ah[4 * k], &Bzh[8 + k * 2]);
                mma16816(cB, &Ah[4 * k], &Bzl[8 + k * 2]);
                mma16816(cB, &Al[4 * k], &Bzh[8 + k * 2]);
            }
            float h[2][4];
            h[0][0] = fmaxf(cA[0] + b2zc[0], 0.f); h[0][1] = fmaxf(cA[1] + b2zc[1], 0.f);
            h[0][2] = fmaxf(cB[0] + b2zc[2], 0.f); h[0][3] = fmaxf(cB[1] + b2zc[3], 0.f);
            h[1][0] = fmaxf(cA[2] + b2zc[0], 0.f); h[1][1] = fmaxf(cA[3] + b2zc[1], 0.f);
            h[1][2] = fmaxf(cB[2] + b2zc[2], 0.f); h[1][3] = fmaxf(cB[3] + b2zc[3], 0.f);
            #pragma unroll
            for (int ri = 0; ri < 2; ri++) {
                float v0 = h[ri][0]*wz0[0] + h[ri][1]*wz0[1] + h[ri][2]*wz0[2] + h[ri][3]*wz0[3];
                float v1 = h[ri][0]*wz1[0] + h[ri][1]*wz1[1] + h[ri][2]*wz1[2] + h[ri][3]*wz1[3];
                float v2 = h[ri][0]*wz2[0] + h[ri][1]*wz2[1] + h[ri][2]*wz2[2] + h[ri][3]*wz2[3];
                v0 += __shfl_xor_sync(0xffffffffu, v0, 1); v0 += __shfl_xor_sync(0xffffffffu, v0, 2);
                v1 += __shfl_xor_sync(0xffffffffu, v1, 1); v1 += __shfl_xor_sync(0xffffffffu, v1, 2);
                v2 += __shfl_xor_sync(0xffffffffu, v2, 1); v2 += __shfl_xor_sync(0xffffffffu, v2, 2);
                if (tg == 0) {
                    int row = m * 16 + ri * 8 + g;
                    *(float*)(smemc + P_Z0 + (row * 4 + wid) * 4) = v0;
                    *(float*)(smemc + P_Z1 + (row * 4 + wid) * 4) = v1;
                    *(float*)(smemc + P_Z2 + (row * 4 + wid) * 4) = v2;
                }
            }
        }

        // ---- q trunk ----
        #pragma unroll 1
        for (int m = 0; m < 8; m++) {
            u32 Ah[16], Al[16];
            #pragma unroll
            for (int k = 0; k < 4; k++) {
                ldsm4(&Ah[4 * k], sb + A_QH + m * 2048 + offk[k]);
                ldsm4(&Al[4 * k], sb + A_QL + m * 2048 + offk[k]);
            }
            float cA[4] = {0, 0, 0, 0}, cB[4] = {0, 0, 0, 0};
            #pragma unroll
            for (int k = 0; k < 4; k++) {
                mma16816(cA, &Ah[4 * k], &Bqh[k * 2]);
                mma16816(cA, &Ah[4 * k], &Bql[k * 2]);
                mma16816(cA, &Al[4 * k], &Bqh[k * 2]);
                mma16816(cB, &Ah[4 * k], &Bqh[8 + k * 2]);
                mma16816(cB, &Ah[4 * k], &Bql[8 + k * 2]);
                mma16816(cB, &Al[4 * k], &Bqh[8 + k * 2]);
            }
            float h[2][4];
            h[0][0] = fmaxf(cA[0] + b2qc[0], 0.f); h[0][1] = fmaxf(cA[1] + b2qc[1], 0.f);
            h[0][2] = fmaxf(cB[0] + b2qc[2], 0.f); h[0][3] = fmaxf(cB[1] + b2qc[3], 0.f);
            h[1][0] = fmaxf(cA[2] + b2qc[0], 0.f); h[1][1] = fmaxf(cA[3] + b2qc[1], 0.f);
            h[1][2] = fmaxf(cB[2] + b2qc[2], 0.f); h[1][3] = fmaxf(cB[3] + b2qc[3], 0.f);
            #pragma unroll
            for (int ri = 0; ri < 2; ri++) {
                float v = h[ri][0]*wqc[0] + h[ri][1]*wqc[1] + h[ri][2]*wqc[2] + h[ri][3]*wqc[3];
                v += __shfl_xor_sync(0xffffffffu, v, 1); v += __shfl_xor_sync(0xffffffffu, v, 2);
                if (tg == 0) {
                    int row = m * 16 + ri * 8 + g;
                    *(float*)(smemc + P_Q + (row * 4 + wid) * 4) = v;
                }
            }
        }
        __syncthreads();

        // ---- gather partials, SDE update ----
        float4 p0 = *(const float4*)(smemc + P_Z0 + tid * 16);
        float4 p1 = *(const float4*)(smemc + P_Z1 + tid * 16);
        float4 p2 = *(const float4*)(smemc + P_Z2 + tid * 16);
        float4 pq = *(const float4*)(smemc + P_Q  + tid * 16);
        float z0 = zb3_0 + p0.x + p0.y + p0.z + p0.w;
        float z1 = zb3_1 + p1.x + p1.y + p1.z + p1.w;
        float z2 = zb3_2 + p2.x + p2.y + p2.z + p2.w;
        float q  = qb3_0 + pq.x + pq.y + pq.z + pq.w;

        float f  = 0.5f * q * q;
        float s0 = 0.2f + 0.1f * tanhf(y0);
        float s1 = 0.2f + 0.1f * tanhf(y1);
        float s2 = 0.2f + 0.1f * tanhf(y2);
        y0 += (q - y0) * dt + s0 * dw0;
        y1 += (q - y1) * dt + s1 * dw1;
        y2 += (q - y2) * dt + s2 * dw2;
        Y  += -f * dt + z0 * dw0 + z1 * dw1 + z2 * dw2;
        __syncthreads();   // partial reads done before next step's P writes
    }

    // ---- per-path loss + deterministic reduction ----
    float term = y0 * y0 + y1 * y1 + y2 * y2;
    float v = Y - term;
    v = v * v;
    #pragma unroll
    for (int off = 16; off > 0; off >>= 1)
        v += __shfl_down_sync(0xffffffffu, v, off);
    if ((tid & 31) == 0) s_red[wid] = v;
    __syncthreads();
    if (tid == 0) {
        g_part[blockIdx.x] = s_red[0] + s_red[1] + s_red[2] + s_red[3];
        __threadfence();
        int c = atomicAdd(&g_cnt, 1);
        s_last = (c == NBLK - 1);
    }
    __syncthreads();
    if (s_last) {
        __threadfence();
        float acc = 0.0f;
        for (int i = tid; i < NBLK; i += TPB) acc += g_part[i];
        #pragma unroll
        for (int off = 16; off > 0; off >>= 1)
            acc += __shfl_down_sync(0xffffffffu, acc, off);
        if ((tid & 31) == 0) s_red[wid] = acc;
        __syncthreads();
        if (tid == 0) {
            out[0] = (s_red[0] + s_red[1] + s_red[2] + s_red[3]) * (1.0f / (float)BATCH);
            g_cnt = 0;   // reset for next replay
        }
    }
}

extern "C" void kernel_launch(void* const* d_in, const int* in_sizes, int n_in,
                              void* d_out, int out_size) {
    const float* y0  = (const float*)d_in[0];
    const float* Y0  = (const float*)d_in[1];
    const float* qW1 = (const float*)d_in[2];
    const float* qb1 = (const float*)d_in[3];
    const float* qW2 = (const float*)d_in[4];
    const float* qb2 = (const float*)d_in[5];
    const float* qW3 = (const float*)d_in[6];
    const float* qb3 = (const float*)d_in[7];
    const float* zW1 = (const float*)d_in[8];
    const float* zb1 = (const float*)d_in[9];
    const float* zW2 = (const float*)d_in[10];
    const float* zb2 = (const float*)d_in[11];
    const float* zW3 = (const float*)d_in[12];
    const float* zb3 = (const float*)d_in[13];
    const float* dW  = (const float*)d_in[14];

    static int attr_done = 0;
    if (!attr_done) {
        cudaFuncSetAttribute(bsde_kernel,
                             cudaFuncAttributeMaxDynamicSharedMemorySize, SMEM_BYTES);
        attr_done = 1;
    }

    bsde_kernel<<<NBLK, TPB, SMEM_BYTES>>>(y0, Y0, qW1, qb1, qW2, qb2, qW3, qb3,
                                           zW1, zb1, zW2, zb2, zW3, zb3, dW, (float*)d_out);
}

// round 9
// speedup vs baseline: 9.5496x; 1.7812x over previous
#include <cuda_runtime.h>
#include <cuda_fp16.h>
#include <math.h>
#include <stdint.h>

#define NSTEPS 50
#define BATCH  131072
#define TPB    128
#define NBLK   (BATCH / TPB)   // 1024

static __device__ float g_part[NBLK];
static __device__ int   g_cnt = 0;

typedef unsigned long long u64;
typedef unsigned int u32;

// ---------------- helpers ----------------
__device__ __forceinline__ u32 smem_u32(const void* p) {
    u32 a;
    asm("{ .reg .u64 t; cvta.to.shared.u64 t, %1; cvt.u32.u64 %0, t; }" : "=r"(a) : "l"(p));
    return a;
}
__device__ __forceinline__ u64 pack2(float a, float b) {
    u64 r; asm("mov.b64 %0, {%1, %2};" : "=l"(r) : "r"(__float_as_uint(a)), "r"(__float_as_uint(b))); return r;
}
__device__ __forceinline__ void unpack2(u64 p, float& a, float& b) {
    u32 x, y; asm("mov.b64 {%0, %1}, %2;" : "=r"(x), "=r"(y) : "l"(p));
    a = __uint_as_float(x); b = __uint_as_float(y);
}
__device__ __forceinline__ u64 ffma2(u64 a, u64 b, u64 c) {
    u64 d; asm("fma.rn.f32x2 %0, %1, %2, %3;" : "=l"(d) : "l"(a), "l"(b), "l"(c)); return d;
}
// packed f16x2: lo -> low 16 bits, hi -> high 16 bits
__device__ __forceinline__ u32 cvt_f16x2(float lo, float hi) {
    u32 r; asm("cvt.rn.f16x2.f32 %0, %1, %2;" : "=r"(r) : "f"(hi), "f"(lo)); return r;
}

__device__ __forceinline__ void mma16816(float c[4], const u32 a[4], const u32 b[2]) {
    asm volatile("mma.sync.aligned.m16n8k16.row.col.f32.f16.f16.f32 "
                 "{%0,%1,%2,%3}, {%4,%5,%6,%7}, {%8,%9}, {%0,%1,%2,%3};"
                 : "+f"(c[0]), "+f"(c[1]), "+f"(c[2]), "+f"(c[3])
                 : "r"(a[0]), "r"(a[1]), "r"(a[2]), "r"(a[3]), "r"(b[0]), "r"(b[1]));
}
__device__ __forceinline__ void ldsm4(u32 r[4], u32 addr) {
    asm volatile("ldmatrix.sync.aligned.m8n8.x4.shared.b16 {%0,%1,%2,%3}, [%4];"
                 : "=r"(r[0]), "=r"(r[1]), "=r"(r[2]), "=r"(r[3]) : "r"(addr));
}

// ---- dynamic smem layout (bytes) ----
// A buffers: [128 rows][64 f16] = 128B/row, XOR-swizzled 16B chunks
#define A_Z  0
#define A_Q  16384
#define P_Z0 32768            // [128][4] f32 each
#define P_Z1 (P_Z0 + 2048)
#define P_Z2 (P_Z0 + 4096)
#define P_Q  (P_Z0 + 6144)
#define W1_Z (P_Z0 + 8192)    // 256 floats
#define W1_Q (W1_Z + 1024)
#define B1_Z (W1_Q + 1024)    // 64 floats
#define B1_Q (B1_Z + 256)
#define SMEM_BYTES (B1_Q + 256)   // 43520 B

// layer 1 (fp32, packed f32x2) -> relu -> f16 -> swizzled SMEM row (row = tid)
__device__ __forceinline__ void layer1_store(const float* __restrict__ sW1,
                                             const float* __restrict__ sb1,
                                             float xt, float y0, float y1, float y2,
                                             char* smemc, int offA, int tid) {
    u64 acc[32];
    const u64* bp = (const u64*)sb1;
    #pragma unroll
    for (int j = 0; j < 32; j++) acc[j] = bp[j];
    float xs[4] = {xt, y0, y1, y2};
    #pragma unroll
    for (int r = 0; r < 4; r++) {
        u64 xr = pack2(xs[r], xs[r]);
        const u64* wr = (const u64*)(sW1 + r * 64);
        #pragma unroll
        for (int j = 0; j < 32; j++) acc[j] = ffma2(xr, wr[j], acc[j]);
    }
    u32 hv[32];
    #pragma unroll
    for (int j = 0; j < 32; j++) {
        float a, b; unpack2(acc[j], a, b);
        hv[j] = cvt_f16x2(fmaxf(a, 0.0f), fmaxf(b, 0.0f));
    }
    const int r7 = tid & 7;
    char* row = smemc + offA + tid * 128;
    #pragma unroll
    for (int c = 0; c < 8; c++) {
        int o = ((c ^ r7) << 4);
        *(uint4*)(row + o) = make_uint4(hv[4*c], hv[4*c+1], hv[4*c+2], hv[4*c+3]);
    }
}

__global__ void __launch_bounds__(TPB, 3)
bsde_kernel(const float* __restrict__ y0v, const float* __restrict__ Y0v,
            const float* __restrict__ qW1, const float* __restrict__ qb1,
            const float* __restrict__ qW2, const float* __restrict__ qb2,
            const float* __restrict__ qW3, const float* __restrict__ qb3,
            const float* __restrict__ zW1, const float* __restrict__ zb1,
            const float* __restrict__ zW2, const float* __restrict__ zb2,
            const float* __restrict__ zW3, const float* __restrict__ zb3,
            const float* __restrict__ dW, float* __restrict__ out) {
    extern __shared__ char smemc[];
    __shared__ float s_red[4];
    __shared__ int s_last;

    const int tid  = threadIdx.x;
    const int lane = tid & 31;
    const int wid  = tid >> 5;
    const int g    = lane >> 2;   // row-in-tile group
    const int tg   = lane & 3;    // col-pair group
    const u32 sb   = smem_u32(smemc);

    // ---- stage W1/b1 in SMEM ----
    float* sW1z = (float*)(smemc + W1_Z);
    float* sW1q = (float*)(smemc + W1_Q);
    float* sb1z = (float*)(smemc + B1_Z);
    float* sb1q = (float*)(smemc + B1_Q);
    for (int i = tid; i < 256; i += TPB) { sW1z[i] = zW1[i]; sW1q[i] = qW1[i]; }
    if (tid < 64) { sb1z[tid] = zb1[tid]; sb1q[tid] = qb1[tid]; }

    // ---- per-thread layer-3 / bias preloads (4 owned columns) ----
    const int col0 = wid * 16 + tg * 2;     // cols: col0, col0+1, col0+8, col0+9
    float b2zc[4], b2qc[4], wz0[4], wz1[4], wz2[4], wqc[4];
    #pragma unroll
    for (int i = 0; i < 4; i++) {
        int c = col0 + (i >> 1) * 8 + (i & 1);
        b2zc[i] = zb2[c]; b2qc[i] = qb2[c];
        wz0[i] = zW3[c * 3 + 0]; wz1[i] = zW3[c * 3 + 1]; wz2[i] = zW3[c * 3 + 2];
        wqc[i] = qW3[c];
    }

    // ---- B fragments (W2 as f16), resident in registers ----
    // idx = nt*8 + kt*2 + r ; pair (k0, k0+1), k0 = kt*16 + tg*2 + r*8, n = wid*16 + nt*8 + g
    u32 Bz[16], Bq[16];
    #pragma unroll
    for (int nt = 0; nt < 2; nt++) {
        int nn = wid * 16 + nt * 8 + g;
        #pragma unroll
        for (int kt = 0; kt < 4; kt++) {
            #pragma unroll
            for (int r = 0; r < 2; r++) {
                int k0 = kt * 16 + tg * 2 + r * 8;
                int idx = nt * 8 + kt * 2 + r;
                Bz[idx] = cvt_f16x2(zW2[k0 * 64 + nn], zW2[(k0 + 1) * 64 + nn]);
                Bq[idx] = cvt_f16x2(qW2[k0 * 64 + nn], qW2[(k0 + 1) * 64 + nn]);
            }
        }
    }

    // ---- ldmatrix per-lane offsets (row-swizzled) ----
    const int mat = lane >> 3, r8 = lane & 7;
    const int rowLocal = (mat & 1) * 8 + r8;
    u32 offk[4];
    #pragma unroll
    for (int k = 0; k < 4; k++)
        offk[k] = (u32)(rowLocal * 128 + ((((k << 1) + (mat >> 1)) ^ r8) << 4));

    const float zb3_0 = zb3[0], zb3_1 = zb3[1], zb3_2 = zb3[2], qb3_0 = qb3[0];
    const int gp = blockIdx.x * TPB + tid;
    const float dt = 0.02f;
    const float sqdt = sqrtf(dt);
    float y0 = y0v[0], y1 = y0v[1], y2 = y0v[2];
    float Y  = Y0v[0];
    __syncthreads();

    for (int n = 0; n < NSTEPS; n++) {
        const float* dwp = dW + ((size_t)n * BATCH + gp) * 3;
        float dw0 = dwp[0] * sqdt;
        float dw1 = dwp[1] * sqdt;
        float dw2 = dwp[2] * sqdt;
        float t = (float)n * dt;

        // ---- layer 1 for both MLPs (fp32), store f16 A operands ----
        layer1_store(sW1z, sb1z, t, y0, y1, y2, smemc, A_Z, tid);
        layer1_store(sW1q, sb1q, t, y0, y1, y2, smemc, A_Q, tid);
        __syncthreads();

        // ---- merged layer-2 GEMMs + fused layer-3 partials ----
        #pragma unroll 1
        for (int m = 0; m < 8; m++) {
            u32 Az[16], Aq[16];
            #pragma unroll
            for (int k = 0; k < 4; k++) {
                ldsm4(&Az[4 * k], sb + A_Z + m * 2048 + offk[k]);
                ldsm4(&Aq[4 * k], sb + A_Q + m * 2048 + offk[k]);
            }
            float cAz[4] = {0,0,0,0}, cBz[4] = {0,0,0,0};
            float cAq[4] = {0,0,0,0}, cBq[4] = {0,0,0,0};
            #pragma unroll
            for (int k = 0; k < 4; k++) {
                mma16816(cAz, &Az[4 * k], &Bz[k * 2]);
                mma16816(cBz, &Az[4 * k], &Bz[8 + k * 2]);
                mma16816(cAq, &Aq[4 * k], &Bq[k * 2]);
                mma16816(cBq, &Aq[4 * k], &Bq[8 + k * 2]);
            }
            // z epilogue for this m-tile
            {
                float h[2][4];
                h[0][0] = fmaxf(cAz[0] + b2zc[0], 0.f); h[0][1] = fmaxf(cAz[1] + b2zc[1], 0.f);
                h[0][2] = fmaxf(cBz[0] + b2zc[2], 0.f); h[0][3] = fmaxf(cBz[1] + b2zc[3], 0.f);
                h[1][0] = fmaxf(cAz[2] + b2zc[0], 0.f); h[1][1] = fmaxf(cAz[3] + b2zc[1], 0.f);
                h[1][2] = fmaxf(cBz[2] + b2zc[2], 0.f); h[1][3] = fmaxf(cBz[3] + b2zc[3], 0.f);
                #pragma unroll
                for (int ri = 0; ri < 2; ri++) {
                    float v0 = h[ri][0]*wz0[0] + h[ri][1]*wz0[1] + h[ri][2]*wz0[2] + h[ri][3]*wz0[3];
                    float v1 = h[ri][0]*wz1[0] + h[ri][1]*wz1[1] + h[ri][2]*wz1[2] + h[ri][3]*wz1[3];
                    float v2 = h[ri][0]*wz2[0] + h[ri][1]*wz2[1] + h[ri][2]*wz2[2] + h[ri][3]*wz2[3];
                    v0 += __shfl_xor_sync(0xffffffffu, v0, 1); v0 += __shfl_xor_sync(0xffffffffu, v0, 2);
                    v1 += __shfl_xor_sync(0xffffffffu, v1, 1); v1 += __shfl_xor_sync(0xffffffffu, v1, 2);
                    v2 += __shfl_xor_sync(0xffffffffu, v2, 1); v2 += __shfl_xor_sync(0xffffffffu, v2, 2);
                    if (tg == 0) {
                        int row = m * 16 + ri * 8 + g;
                        *(float*)(smemc + P_Z0 + (row * 4 + wid) * 4) = v0;
                        *(float*)(smemc + P_Z1 + (row * 4 + wid) * 4) = v1;
                        *(float*)(smemc + P_Z2 + (row * 4 + wid) * 4) = v2;
                    }
                }
            }
            // q epilogue for this m-tile
            {
                float h[2][4];
                h[0][0] = fmaxf(cAq[0] + b2qc[0], 0.f); h[0][1] = fmaxf(cAq[1] + b2qc[1], 0.f);
                h[0][2] = fmaxf(cBq[0] + b2qc[2], 0.f); h[0][3] = fmaxf(cBq[1] + b2qc[3], 0.f);
                h[1][0] = fmaxf(cAq[2] + b2qc[0], 0.f); h[1][1] = fmaxf(cAq[3] + b2qc[1], 0.f);
                h[1][2] = fmaxf(cBq[2] + b2qc[2], 0.f); h[1][3] = fmaxf(cBq[3] + b2qc[3], 0.f);
                #pragma unroll
                for (int ri = 0; ri < 2; ri++) {
                    float v = h[ri][0]*wqc[0] + h[ri][1]*wqc[1] + h[ri][2]*wqc[2] + h[ri][3]*wqc[3];
                    v += __shfl_xor_sync(0xffffffffu, v, 1); v += __shfl_xor_sync(0xffffffffu, v, 2);
                    if (tg == 0) {
                        int row = m * 16 + ri * 8 + g;
                        *(float*)(smemc + P_Q + (row * 4 + wid) * 4) = v;
                    }
                }
            }
        }
        __syncthreads();

        // ---- gather partials, SDE update ----
        float4 p0 = *(const float4*)(smemc + P_Z0 + tid * 16);
        float4 p1 = *(const float4*)(smemc + P_Z1 + tid * 16);
        float4 p2 = *(const float4*)(smemc + P_Z2 + tid * 16);
        float4 pq = *(const float4*)(smemc + P_Q  + tid * 16);
        float z0 = zb3_0 + p0.x + p0.y + p0.z + p0.w;
        float z1 = zb3_1 + p1.x + p1.y + p1.z + p1.w;
        float z2 = zb3_2 + p2.x + p2.y + p2.z + p2.w;
        float q  = qb3_0 + pq.x + pq.y + pq.z + pq.w;

        float f  = 0.5f * q * q;
        float s0 = 0.2f + 0.1f * tanhf(y0);
        float s1 = 0.2f + 0.1f * tanhf(y1);
        float s2 = 0.2f + 0.1f * tanhf(y2);
        y0 += (q - y0) * dt + s0 * dw0;
        y1 += (q - y1) * dt + s1 * dw1;
        y2 += (q - y2) * dt + s2 * dw2;
        Y  += -f * dt + z0 * dw0 + z1 * dw1 + z2 * dw2;
        __syncthreads();   // partial reads done before next step's writes
    }

    // ---- per-path loss + deterministic reduction ----
    float term = y0 * y0 + y1 * y1 + y2 * y2;
    float v = Y - term;
    v = v * v;
    #pragma unroll
    for (int off = 16; off > 0; off >>= 1)
        v += __shfl_down_sync(0xffffffffu, v, off);
    if ((tid & 31) == 0) s_red[wid] = v;
    __syncthreads();
    if (tid == 0) {
        g_part[blockIdx.x] = s_red[0] + s_red[1] + s_red[2] + s_red[3];
        __threadfence();
        int c = atomicAdd(&g_cnt, 1);
        s_last = (c == NBLK - 1);
    }
    __syncthreads();
    if (s_last) {
        __threadfence();
        float acc = 0.0f;
        for (int i = tid; i < NBLK; i += TPB) acc += g_part[i];
        #pragma unroll
        for (int off = 16; off > 0; off >>= 1)
            acc += __shfl_down_sync(0xffffffffu, acc, off);
        if ((tid & 31) == 0) s_red[wid] = acc;
        __syncthreads();
        if (tid == 0) {
            out[0] = (s_red[0] + s_red[1] + s_red[2] + s_red[3]) * (1.0f / (float)BATCH);
            g_cnt = 0;   // reset for next replay
        }
    }
}

extern "C" void kernel_launch(void* const* d_in, const int* in_sizes, int n_in,
                              void* d_out, int out_size) {
    const float* y0  = (const float*)d_in[0];
    const float* Y0  = (const float*)d_in[1];
    const float* qW1 = (const float*)d_in[2];
    const float* qb1 = (const float*)d_in[3];
    const float* qW2 = (const float*)d_in[4];
    const float* qb2 = (const float*)d_in[5];
    const float* qW3 = (const float*)d_in[6];
    const float* qb3 = (const float*)d_in[7];
    const float* zW1 = (const float*)d_in[8];
    const float* zb1 = (const float*)d_in[9];
    const float* zW2 = (const float*)d_in[10];
    const float* zb2 = (const float*)d_in[11];
    const float* zW3 = (const float*)d_in[12];
    const float* zb3 = (const float*)d_in[13];
    const float* dW  = (const float*)d_in[14];

    static int attr_done = 0;
    if (!attr_done) {
        cudaFuncSetAttribute(bsde_kernel,
                             cudaFuncAttributeMaxDynamicSharedMemorySize, SMEM_BYTES);
        attr_done = 1;
    }

    bsde_kernel<<<NBLK, TPB, SMEM_BYTES>>>(y0, Y0, qW1, qb1, qW2, qb2, qW3, qb3,
                                           zW1, zb1, zW2, zb2, zW3, zb3, dW, (float*)d_out);
}

// round 10
// speedup vs baseline: 9.5635x; 1.0015x over previous
#include <cuda_runtime.h>
#include <cuda_fp16.h>
#include <math.h>
#include <stdint.h>

#define NSTEPS 50
#define BATCH  131072
#define TPB    128
#define NBLK   (BATCH / TPB)   // 1024

static __device__ float g_part[NBLK];
static __device__ int   g_cnt = 0;

typedef unsigned long long u64;
typedef unsigned int u32;

__device__ __forceinline__ u32 smem_u32(const void* p) {
    u32 a;
    asm("{ .reg .u64 t; cvta.to.shared.u64 t, %1; cvt.u32.u64 %0, t; }" : "=r"(a) : "l"(p));
    return a;
}
__device__ __forceinline__ u64 pack2(float a, float b) {
    u64 r; asm("mov.b64 %0, {%1, %2};" : "=l"(r) : "r"(__float_as_uint(a)), "r"(__float_as_uint(b))); return r;
}
__device__ __forceinline__ void unpack2(u64 p, float& a, float& b) {
    u32 x, y; asm("mov.b64 {%0, %1}, %2;" : "=r"(x), "=r"(y) : "l"(p));
    a = __uint_as_float(x); b = __uint_as_float(y);
}
__device__ __forceinline__ u64 ffma2(u64 a, u64 b, u64 c) {
    u64 d; asm("fma.rn.f32x2 %0, %1, %2, %3;" : "=l"(d) : "l"(a), "l"(b), "l"(c)); return d;
}
__device__ __forceinline__ u32 cvt_f16x2(float lo, float hi) {
    u32 r; asm("cvt.rn.f16x2.f32 %0, %1, %2;" : "=r"(r) : "f"(hi), "f"(lo)); return r;
}
__device__ __forceinline__ void mma16816(float c[4], const u32 a[4], const u32 b[2]) {
    asm volatile("mma.sync.aligned.m16n8k16.row.col.f32.f16.f16.f32 "
                 "{%0,%1,%2,%3}, {%4,%5,%6,%7}, {%8,%9}, {%0,%1,%2,%3};"
                 : "+f"(c[0]), "+f"(c[1]), "+f"(c[2]), "+f"(c[3])
                 : "r"(a[0]), "r"(a[1]), "r"(a[2]), "r"(a[3]), "r"(b[0]), "r"(b[1]));
}
__device__ __forceinline__ void ldsm4(u32 r[4], u32 addr) {
    asm volatile("ldmatrix.sync.aligned.m8n8.x4.shared.b16 {%0,%1,%2,%3}, [%4];"
                 : "=r"(r[0]), "=r"(r[1]), "=r"(r[2]), "=r"(r[3]) : "r"(addr));
}

// layer 1 (fp32) -> relu -> f16 -> swizzled SMEM row; two 32-neuron passes (reg pressure)
__device__ __forceinline__ void layer1_store(const float* __restrict__ sW1,
                                             const float* __restrict__ sb1,
                                             float xt, float y0, float y1, float y2,
                                             char* rowp, int r7) {
    #pragma unroll
    for (int half = 0; half < 2; half++) {
        u64 acc[16];
        const u64* bp = (const u64*)(sb1 + half * 32);
        #pragma unroll
        for (int j = 0; j < 16; j++) acc[j] = bp[j];
        float xs[4] = {xt, y0, y1, y2};
        #pragma unroll
        for (int r = 0; r < 4; r++) {
            u64 xr = pack2(xs[r], xs[r]);
            const u64* wr = (const u64*)(sW1 + r * 64 + half * 32);
            #pragma unroll
            for (int j = 0; j < 16; j++) acc[j] = ffma2(xr, wr[j], acc[j]);
        }
        u32 hv[16];
        #pragma unroll
        for (int j = 0; j < 16; j++) {
            float a, b; unpack2(acc[j], a, b);
            hv[j] = cvt_f16x2(fmaxf(a, 0.0f), fmaxf(b, 0.0f));
        }
        #pragma unroll
        for (int c = 0; c < 4; c++) {
            int o = (((half * 4 + c) ^ r7) << 4);
            *(uint4*)(rowp + o) = make_uint4(hv[4*c], hv[4*c+1], hv[4*c+2], hv[4*c+3]);
        }
    }
}

__global__ void __launch_bounds__(TPB, 3)
bsde_kernel(const float* __restrict__ y0v, const float* __restrict__ Y0v,
            const float* __restrict__ qW1, const float* __restrict__ qb1,
            const float* __restrict__ qW2, const float* __restrict__ qb2,
            const float* __restrict__ qW3, const float* __restrict__ qb3,
            const float* __restrict__ zW1, const float* __restrict__ zb1,
            const float* __restrict__ zW2, const float* __restrict__ zb2,
            const float* __restrict__ zW3, const float* __restrict__ zb3,
            const float* __restrict__ dW, float* __restrict__ out) {
    __shared__ __align__(16) char sA[32768];     // A_Z [0,16K), A_Q [16K,32K)
    __shared__ __align__(8) float sPZ0[256], sPZ1[256], sPZ2[256], sPQ[256];
    __shared__ __align__(16) float sW1z[256], sW1q[256], sb1z[64], sb1q[64];
    __shared__ float s_red[4];
    __shared__ int s_last;

    const int tid  = threadIdx.x;
    const int lane = tid & 31;
    const int wid  = tid >> 5;
    const int g    = lane >> 2;
    const int tg   = lane & 3;
    const int trunk = wid >> 1;     // 0 = z, 1 = q
    const int nhalf = wid & 1;      // N cols [32*nhalf, 32*nhalf+32)
    const u32 sb = smem_u32(sA);

    // ---- stage W1/b1 ----
    for (int i = tid; i < 256; i += TPB) { sW1z[i] = zW1[i]; sW1q[i] = qW1[i]; }
    if (tid < 64) { sb1z[tid] = zb1[tid]; sb1q[tid] = qb1[tid]; }

    // ---- per-thread epilogue constants (8 owned cols) ----
    float b2c[8], w0c[8], w1c[8], w2c[8];
    #pragma unroll
    for (int i = 0; i < 8; i++) {
        int col = nhalf * 32 + (i >> 1) * 8 + tg * 2 + (i & 1);
        if (trunk == 0) {
            b2c[i] = zb2[col];
            w0c[i] = zW3[col * 3 + 0];
            w1c[i] = zW3[col * 3 + 1];
            w2c[i] = zW3[col * 3 + 2];
        } else {
            b2c[i] = qb2[col];
            w0c[i] = qW3[col];
            w1c[i] = 0.0f;
            w2c[i] = 0.0f;
        }
    }

    // ---- B fragments (one trunk, 4 n-tiles x 4 k-tiles x 2) ----
    const float* W2 = trunk ? qW2 : zW2;
    u32 Bf[32];
    #pragma unroll
    for (int nt = 0; nt < 4; nt++) {
        int nn = nhalf * 32 + nt * 8 + g;
        #pragma unroll
        for (int kt = 0; kt < 4; kt++) {
            #pragma unroll
            for (int r = 0; r < 2; r++) {
                int k0 = kt * 16 + tg * 2 + r * 8;
                Bf[nt * 8 + kt * 2 + r] = cvt_f16x2(W2[k0 * 64 + nn], W2[(k0 + 1) * 64 + nn]);
            }
        }
    }

    // ---- ldmatrix per-lane offsets ----
    const int mat = lane >> 3, r8 = lane & 7;
    const int rowLocal = (mat & 1) * 8 + r8;
    u32 offk[4];
    #pragma unroll
    for (int k = 0; k < 4; k++)
        offk[k] = (u32)(rowLocal * 128 + ((((k << 1) + (mat >> 1)) ^ r8) << 4));
    const u32 Abase = sb + trunk * 16384;

    const float zb3_0 = zb3[0], zb3_1 = zb3[1], zb3_2 = zb3[2], qb3_0 = qb3[0];
    const int gp = blockIdx.x * TPB + tid;
    const float dt = 0.02f;
    const float sqdt = sqrtf(dt);
    float y0 = y0v[0], y1 = y0v[1], y2 = y0v[2];
    float Y  = Y0v[0];
    char* rowZ = sA + tid * 128;
    char* rowQ = sA + 16384 + tid * 128;
    const int r7 = tid & 7;
    __syncthreads();

    for (int n = 0; n < NSTEPS; n++) {
        const float* dwp = dW + ((size_t)n * BATCH + gp) * 3;
        float dw0 = dwp[0] * sqdt;
        float dw1 = dwp[1] * sqdt;
        float dw2 = dwp[2] * sqdt;
        float t = (float)n * dt;

        // ---- layer 1 both MLPs (thread = its path's row) ----
        layer1_store(sW1z, sb1z, t, y0, y1, y2, rowZ, r7);
        layer1_store(sW1q, sb1q, t, y0, y1, y2, rowQ, r7);
        __syncthreads();   // A ready

        // ---- this warp's trunk GEMM over all 8 m-tiles ----
        #pragma unroll 1
        for (int mt = 0; mt < 8; mt++) {
            u32 Am[16];
            #pragma unroll
            for (int kt = 0; kt < 4; kt++)
                ldsm4(&Am[4 * kt], Abase + mt * 2048 + offk[kt]);
            float c[4][4] = {{0,0,0,0},{0,0,0,0},{0,0,0,0},{0,0,0,0}};
            #pragma unroll
            for (int kt = 0; kt < 4; kt++) {
                #pragma unroll
                for (int nt = 0; nt < 4; nt++)
                    mma16816(c[nt], &Am[4 * kt], &Bf[nt * 8 + kt * 2]);
            }
            // ---- fused layer-3 partials ----
            #pragma unroll
            for (int ri = 0; ri < 2; ri++) {
                float a0 = 0.f, a1 = 0.f, a2 = 0.f;
                #pragma unroll
                for (int nt = 0; nt < 4; nt++) {
                    #pragma unroll
                    for (int j = 0; j < 2; j++) {
                        int i = nt * 2 + j;
                        float h = fmaxf(c[nt][ri * 2 + j] + b2c[i], 0.0f);
                        a0 += h * w0c[i];
                        a1 += h * w1c[i];
                        a2 += h * w2c[i];
                    }
                }
                a0 += __shfl_xor_sync(0xffffffffu, a0, 1);
                a0 += __shfl_xor_sync(0xffffffffu, a0, 2);
                a1 += __shfl_xor_sync(0xffffffffu, a1, 1);
                a1 += __shfl_xor_sync(0xffffffffu, a1, 2);
                a2 += __shfl_xor_sync(0xffffffffu, a2, 1);
                a2 += __shfl_xor_sync(0xffffffffu, a2, 2);
                if (tg == 0) {
                    int row = mt * 16 + ri * 8 + g;
                    if (trunk == 0) {
                        sPZ0[row * 2 + nhalf] = a0;
                        sPZ1[row * 2 + nhalf] = a1;
                        sPZ2[row * 2 + nhalf] = a2;
                    } else {
                        sPQ[row * 2 + nhalf] = a0;
                    }
                }
            }
        }
        __syncthreads();   // P ready (also orders A reads before next overwrite)

        // ---- gather, SDE update ----
        float2 p0 = *(const float2*)&sPZ0[tid * 2];
        float2 p1 = *(const float2*)&sPZ1[tid * 2];
        float2 p2 = *(const float2*)&sPZ2[tid * 2];
        float2 pq = *(const float2*)&sPQ[tid * 2];
        float z0 = zb3_0 + p0.x + p0.y;
        float z1 = zb3_1 + p1.x + p1.y;
        float z2 = zb3_2 + p2.x + p2.y;
        float q  = qb3_0 + pq.x + pq.y;

        float f  = 0.5f * q * q;
        float s0 = 0.2f + 0.1f * tanhf(y0);
        float s1 = 0.2f + 0.1f * tanhf(y1);
        float s2 = 0.2f + 0.1f * tanhf(y2);
        y0 += (q - y0) * dt + s0 * dw0;
        y1 += (q - y1) * dt + s1 * dw1;
        y2 += (q - y2) * dt + s2 * dw2;
        Y  += -f * dt + z0 * dw0 + z1 * dw1 + z2 * dw2;
        // next iteration's top barrier orders P reads before new P writes
    }

    // ---- per-path loss + deterministic reduction ----
    float term = y0 * y0 + y1 * y1 + y2 * y2;
    float v = Y - term;
    v = v * v;
    #pragma unroll
    for (int off = 16; off > 0; off >>= 1)
        v += __shfl_down_sync(0xffffffffu, v, off);
    if ((tid & 31) == 0) s_red[wid] = v;
    __syncthreads();
    if (tid == 0) {
        g_part[blockIdx.x] = s_red[0] + s_red[1] + s_red[2] + s_red[3];
        __threadfence();
        int c = atomicAdd(&g_cnt, 1);
        s_last = (c == NBLK - 1);
    }
    __syncthreads();
    if (s_last) {
        __threadfence();
        float acc = 0.0f;
        for (int i = tid; i < NBLK; i += TPB) acc += g_part[i];
        #pragma unroll
        for (int off = 16; off > 0; off >>= 1)
            acc += __shfl_down_sync(0xffffffffu, acc, off);
        if ((tid & 31) == 0) s_red[wid] = acc;
        __syncthreads();
        if (tid == 0) {
            out[0] = (s_red[0] + s_red[1] + s_red[2] + s_red[3]) * (1.0f / (float)BATCH);
            g_cnt = 0;   // reset for next replay
        }
    }
}

extern "C" void kernel_launch(void* const* d_in, const int* in_sizes, int n_in,
                              void* d_out, int out_size) {
    const float* y0  = (const float*)d_in[0];
    const float* Y0  = (const float*)d_in[1];
    const float* qW1 = (const float*)d_in[2];
    const float* qb1 = (const float*)d_in[3];
    const float* qW2 = (const float*)d_in[4];
    const float* qb2 = (const float*)d_in[5];
    const float* qW3 = (const float*)d_in[6];
    const float* qb3 = (const float*)d_in[7];
    const float* zW1 = (const float*)d_in[8];
    const float* zb1 = (const float*)d_in[9];
    const float* zW2 = (const float*)d_in[10];
    const float* zb2 = (const float*)d_in[11];
    const float* zW3 = (const float*)d_in[12];
    const float* zb3 = (const float*)d_in[13];
    const float* dW  = (const float*)d_in[14];

    bsde_kernel<<<NBLK, TPB>>>(y0, Y0, qW1, qb1, qW2, qb2, qW3, qb3,
                               zW1, zb1, zW2, zb2, zW3, zb3, dW, (float*)d_out);
}

// round 11
// speedup vs baseline: 12.4447x; 1.3013x over previous
#include <cuda_runtime.h>
#include <cuda_fp16.h>
#include <math.h>
#include <stdint.h>

#define NSTEPS 50
#define BATCH  131072
#define TPB    128
#define NBLK   (BATCH / TPB)   // 1024

static __device__ float g_part[NBLK];
static __device__ int   g_cnt = 0;

typedef unsigned long long u64;
typedef unsigned int u32;

__device__ __forceinline__ u32 smem_u32(const void* p) {
    u32 a;
    asm("{ .reg .u64 t; cvta.to.shared.u64 t, %1; cvt.u32.u64 %0, t; }" : "=r"(a) : "l"(p));
    return a;
}
__device__ __forceinline__ u64 pack2(float a, float b) {
    u64 r; asm("mov.b64 %0, {%1, %2};" : "=l"(r) : "r"(__float_as_uint(a)), "r"(__float_as_uint(b))); return r;
}
__device__ __forceinline__ void unpack2(u64 p, float& a, float& b) {
    u32 x, y; asm("mov.b64 {%0, %1}, %2;" : "=r"(x), "=r"(y) : "l"(p));
    a = __uint_as_float(x); b = __uint_as_float(y);
}
__device__ __forceinline__ u64 ffma2(u64 a, u64 b, u64 c) {
    u64 d; asm("fma.rn.f32x2 %0, %1, %2, %3;" : "=l"(d) : "l"(a), "l"(b), "l"(c)); return d;
}
__device__ __forceinline__ u32 cvt_f16x2(float lo, float hi) {
    u32 r; asm("cvt.rn.f16x2.f32 %0, %1, %2;" : "=r"(r) : "f"(hi), "f"(lo)); return r;
}
__device__ __forceinline__ void mma16816(float c[4], const u32 a[4], const u32 b[2]) {
    asm volatile("mma.sync.aligned.m16n8k16.row.col.f32.f16.f16.f32 "
                 "{%0,%1,%2,%3}, {%4,%5,%6,%7}, {%8,%9}, {%0,%1,%2,%3};"
                 : "+f"(c[0]), "+f"(c[1]), "+f"(c[2]), "+f"(c[3])
                 : "r"(a[0]), "r"(a[1]), "r"(a[2]), "r"(a[3]), "r"(b[0]), "r"(b[1]));
}
__device__ __forceinline__ void ldsm4(u32 r[4], u32 addr) {
    asm volatile("ldmatrix.sync.aligned.m8n8.x4.shared.b16 {%0,%1,%2,%3}, [%4];"
                 : "=r"(r[0]), "=r"(r[1]), "=r"(r[2]), "=r"(r[3]) : "r"(addr));
}

// layer 1 (fp32) -> relu -> f16 -> swizzled SMEM row; two 32-neuron passes (reg pressure)
__device__ __forceinline__ void layer1_store(const float* __restrict__ sW1,
                                             const float* __restrict__ sb1,
                                             float xt, float y0, float y1, float y2,
                                             char* rowp, int r7) {
    #pragma unroll
    for (int half = 0; half < 2; half++) {
        u64 acc[16];
        const u64* bp = (const u64*)(sb1 + half * 32);
        #pragma unroll
        for (int j = 0; j < 16; j++) acc[j] = bp[j];
        float xs[4] = {xt, y0, y1, y2};
        #pragma unroll
        for (int r = 0; r < 4; r++) {
            u64 xr = pack2(xs[r], xs[r]);
            const u64* wr = (const u64*)(sW1 + r * 64 + half * 32);
            #pragma unroll
            for (int j = 0; j < 16; j++) acc[j] = ffma2(xr, wr[j], acc[j]);
        }
        u32 hv[16];
        #pragma unroll
        for (int j = 0; j < 16; j++) {
            float a, b; unpack2(acc[j], a, b);
            hv[j] = cvt_f16x2(fmaxf(a, 0.0f), fmaxf(b, 0.0f));
        }
        #pragma unroll
        for (int c = 0; c < 4; c++) {
            int o = (((half * 4 + c) ^ r7) << 4);
            *(uint4*)(rowp + o) = make_uint4(hv[4*c], hv[4*c+1], hv[4*c+2], hv[4*c+3]);
        }
    }
}

__global__ void __launch_bounds__(TPB, 4)
bsde_kernel(const float* __restrict__ y0v, const float* __restrict__ Y0v,
            const float* __restrict__ qW1, const float* __restrict__ qb1,
            const float* __restrict__ qW2, const float* __restrict__ qb2,
            const float* __restrict__ qW3, const float* __restrict__ qb3,
            const float* __restrict__ zW1, const float* __restrict__ zb1,
            const float* __restrict__ zW2, const float* __restrict__ zb2,
            const float* __restrict__ zW3, const float* __restrict__ zb3,
            const float* __restrict__ dW, float* __restrict__ out) {
    __shared__ __align__(16) char sA[32768];     // A_Z [0,16K), A_Q [16K,32K)
    __shared__ __align__(16) float sP[128 * 8];  // [row][nhalf*4 + {z0,z1,z2,q}]
    __shared__ __align__(16) float sW1z[256], sW1q[256], sb1z[64], sb1q[64];
    __shared__ float s_red[4];
    __shared__ int s_last;

    const int tid  = threadIdx.x;
    const int lane = tid & 31;
    const int wid  = tid >> 5;
    const int g    = lane >> 2;
    const int tg   = lane & 3;
    const int trunk = wid >> 1;     // 0 = z, 1 = q
    const int nhalf = wid & 1;      // N cols [32*nhalf, 32*nhalf+32)
    const u32 sb = smem_u32(sA);

    // ---- stage W1/b1 ----
    for (int i = tid; i < 256; i += TPB) { sW1z[i] = zW1[i]; sW1q[i] = qW1[i]; }
    if (tid < 64) { sb1z[tid] = zb1[tid]; sb1q[tid] = qb1[tid]; }

    // ---- b2 accumulator-init values (per-lane cols) ----
    const float* b2src = trunk ? qb2 : zb2;
    float b2c[8];
    #pragma unroll
    for (int i = 0; i < 8; i++) {
        int col = nhalf * 32 + (i >> 1) * 8 + tg * 2 + (i & 1);
        b2c[i] = b2src[col];
    }

    // ---- B fragments for layer 2 (one trunk, 4 n-tiles x 4 k-tiles x 2) ----
    const float* W2 = trunk ? qW2 : zW2;
    u32 Bf[32];
    #pragma unroll
    for (int nt = 0; nt < 4; nt++) {
        int nn = nhalf * 32 + nt * 8 + g;
        #pragma unroll
        for (int kt = 0; kt < 4; kt++) {
            #pragma unroll
            for (int r = 0; r < 2; r++) {
                int k0 = kt * 16 + tg * 2 + r * 8;
                Bf[nt * 8 + kt * 2 + r] = cvt_f16x2(W2[k0 * 64 + nn], W2[(k0 + 1) * 64 + nn]);
            }
        }
    }

    // ---- B fragments for layer 3 (k = this warp's 32 h2 cols, n = 3 (z) or 1 (q), zero-padded) ----
    u32 B3f[4];
    #pragma unroll
    for (int k2 = 0; k2 < 2; k2++) {
        #pragma unroll
        for (int r = 0; r < 2; r++) {
            int kb = nhalf * 32 + k2 * 16 + tg * 2 + r * 8;
            float w0 = 0.f, w1 = 0.f;
            if (trunk == 0) {
                if (g < 3) { w0 = zW3[kb * 3 + g]; w1 = zW3[(kb + 1) * 3 + g]; }
            } else {
                if (g == 0) { w0 = qW3[kb]; w1 = qW3[kb + 1]; }
            }
            B3f[k2 * 2 + r] = cvt_f16x2(w0, w1);
        }
    }

    // ---- ldmatrix per-lane offsets ----
    const int mat = lane >> 3, r8 = lane & 7;
    const int rowLocal = (mat & 1) * 8 + r8;
    u32 offk[4];
    #pragma unroll
    for (int k = 0; k < 4; k++)
        offk[k] = (u32)(rowLocal * 128 + ((((k << 1) + (mat >> 1)) ^ r8) << 4));
    const u32 Abase = sb + trunk * 16384;

    const float zb3_0 = zb3[0], zb3_1 = zb3[1], zb3_2 = zb3[2], qb3_0 = qb3[0];
    const int gp = blockIdx.x * TPB + tid;
    const float dt = 0.02f;
    const float sqdt = sqrtf(dt);
    float y0 = y0v[0], y1 = y0v[1], y2 = y0v[2];
    float Y  = Y0v[0];
    char* rowZ = sA + tid * 128;
    char* rowQ = sA + 16384 + tid * 128;
    const int r7 = tid & 7;
    __syncthreads();

    for (int n = 0; n < NSTEPS; n++) {
        const float* dwp = dW + ((size_t)n * BATCH + gp) * 3;
        float dw0 = dwp[0] * sqdt;
        float dw1 = dwp[1] * sqdt;
        float dw2 = dwp[2] * sqdt;
        float t = (float)n * dt;

        // ---- layer 1 both MLPs (thread = its path's row) ----
        layer1_store(sW1z, sb1z, t, y0, y1, y2, rowZ, r7);
        layer1_store(sW1q, sb1q, t, y0, y1, y2, rowQ, r7);
        __syncthreads();   // A ready

        // ---- this warp's trunk: layer-2 GEMM (bias-init) + layer-3 GEMM per m-tile ----
        #pragma unroll 1
        for (int mt = 0; mt < 8; mt++) {
            u32 Am[16];
            #pragma unroll
            for (int kt = 0; kt < 4; kt++)
                ldsm4(&Am[4 * kt], Abase + mt * 2048 + offk[kt]);
            // accumulators pre-loaded with b2 (bias before relu)
            float c[4][4];
            #pragma unroll
            for (int nt = 0; nt < 4; nt++) {
                c[nt][0] = b2c[2 * nt];     c[nt][1] = b2c[2 * nt + 1];
                c[nt][2] = b2c[2 * nt];     c[nt][3] = b2c[2 * nt + 1];
            }
            #pragma unroll
            for (int kt = 0; kt < 4; kt++) {
                #pragma unroll
                for (int nt = 0; nt < 4; nt++)
                    mma16816(c[nt], &Am[4 * kt], &Bf[nt * 8 + kt * 2]);
            }
            // ---- layer 3 as MMA: A = relu(h2) f16 (from c frags), B = W3 frags ----
            float c3[4] = {0.f, 0.f, 0.f, 0.f};
            #pragma unroll
            for (int k2 = 0; k2 < 2; k2++) {
                u32 a3[4];
                a3[0] = cvt_f16x2(fmaxf(c[2*k2][0], 0.f),     fmaxf(c[2*k2][1], 0.f));
                a3[1] = cvt_f16x2(fmaxf(c[2*k2][2], 0.f),     fmaxf(c[2*k2][3], 0.f));
                a3[2] = cvt_f16x2(fmaxf(c[2*k2+1][0], 0.f),   fmaxf(c[2*k2+1][1], 0.f));
                a3[3] = cvt_f16x2(fmaxf(c[2*k2+1][2], 0.f),   fmaxf(c[2*k2+1][3], 0.f));
                mma16816(c3, a3, &B3f[k2 * 2]);
            }
            // ---- scatter partials: rows mt*16+g and +8; cols of c3 = {tg*2, tg*2+1} ----
            {
                int row0 = mt * 16 + g;
                float* p0 = &sP[row0 * 8 + nhalf * 4];
                float* p1 = &sP[(row0 + 8) * 8 + nhalf * 4];
                if (trunk == 0) {
                    if (tg == 0) {        // cols 0,1 -> z0,z1
                        *(float2*)(p0 + 0) = make_float2(c3[0], c3[1]);
                        *(float2*)(p1 + 0) = make_float2(c3[2], c3[3]);
                    } else if (tg == 1) { // col 2 -> z2
                        p0[2] = c3[0];
                        p1[2] = c3[2];
                    }
                } else {
                    if (tg == 0) {        // col 0 -> q
                        p0[3] = c3[0];
                        p1[3] = c3[2];
                    }
                }
            }
        }
        __syncthreads();   // P ready (also orders A reads before next overwrite)

        // ---- gather, SDE update ----
        float4 ph0 = *(const float4*)&sP[tid * 8];
        float4 ph1 = *(const float4*)&sP[tid * 8 + 4];
        float z0 = zb3_0 + ph0.x + ph1.x;
        float z1 = zb3_1 + ph0.y + ph1.y;
        float z2 = zb3_2 + ph0.z + ph1.z;
        float q  = qb3_0 + ph0.w + ph1.w;

        float f  = 0.5f * q * q;
        float s0 = 0.2f + 0.1f * tanhf(y0);
        float s1 = 0.2f + 0.1f * tanhf(y1);
        float s2 = 0.2f + 0.1f * tanhf(y2);
        y0 += (q - y0) * dt + s0 * dw0;
        y1 += (q - y1) * dt + s1 * dw1;
        y2 += (q - y2) * dt + s2 * dw2;
        Y  += -f * dt + z0 * dw0 + z1 * dw1 + z2 * dw2;
        // next iteration's top barrier orders P reads before new P writes
    }

    // ---- per-path loss + deterministic reduction ----
    float term = y0 * y0 + y1 * y1 + y2 * y2;
    float v = Y - term;
    v = v * v;
    #pragma unroll
    for (int off = 16; off > 0; off >>= 1)
        v += __shfl_down_sync(0xffffffffu, v, off);
    if ((tid & 31) == 0) s_red[wid] = v;
    __syncthreads();
    if (tid == 0) {
        g_part[blockIdx.x] = s_red[0] + s_red[1] + s_red[2] + s_red[3];
        __threadfence();
        int c = atomicAdd(&g_cnt, 1);
        s_last = (c == NBLK - 1);
    }
    __syncthreads();
    if (s_last) {
        __threadfence();
        float acc = 0.0f;
        for (int i = tid; i < NBLK; i += TPB) acc += g_part[i];
        #pragma unroll
        for (int off = 16; off > 0; off >>= 1)
            acc += __shfl_down_sync(0xffffffffu, acc, off);
        if ((tid & 31) == 0) s_red[wid] = acc;
        __syncthreads();
        if (tid == 0) {
            out[0] = (s_red[0] + s_red[1] + s_red[2] + s_red[3]) * (1.0f / (float)BATCH);
            g_cnt = 0;   // reset for next replay
        }
    }
}

extern "C" void kernel_launch(void* const* d_in, const int* in_sizes, int n_in,
                              void* d_out, int out_size) {
    const float* y0  = (const float*)d_in[0];
    const float* Y0  = (const float*)d_in[1];
    const float* qW1 = (const float*)d_in[2];
    const float* qb1 = (const float*)d_in[3];
    const float* qW2 = (const float*)d_in[4];
    const float* qb2 = (const float*)d_in[5];
    const float* qW3 = (const float*)d_in[6];
    const float* qb3 = (const float*)d_in[7];
    const float* zW1 = (const float*)d_in[8];
    const float* zb1 = (const float*)d_in[9];
    const float* zW2 = (const float*)d_in[10];
    const float* zb2 = (const float*)d_in[11];
    const float* zW3 = (const float*)d_in[12];
    const float* zb3 = (const float*)d_in[13];
    const float* dW  = (const float*)d_in[14];

    bsde_kernel<<<NBLK, TPB>>>(y0, Y0, qW1, qb1, qW2, qb2, qW3, qb3,
                               zW1, zb1, zW2, zb2, zW3, zb3, dW, (float*)d_out);
}

// round 13
// speedup vs baseline: 16.7849x; 1.3488x over previous
#include <cuda_runtime.h>
#include <cuda_fp16.h>
#include <math.h>
#include <stdint.h>

#define NSTEPS 50
#define BATCH  131072
#define TPB    128
#define NBLK   (BATCH / TPB)   // 1024

static __device__ float g_part[NBLK];
static __device__ int   g_cnt = 0;

typedef unsigned long long u64;
typedef unsigned int u32;

__device__ __forceinline__ u32 smem_u32(const void* p) {
    u32 a;
    asm("{ .reg .u64 t; cvta.to.shared.u64 t, %1; cvt.u32.u64 %0, t; }" : "=r"(a) : "l"(p));
    return a;
}
__device__ __forceinline__ u32 cvt_f16x2(float lo, float hi) {
    u32 r; asm("cvt.rn.f16x2.f32 %0, %1, %2;" : "=r"(r) : "f"(hi), "f"(lo)); return r;
}
__device__ __forceinline__ void mma16816(float c[4], const u32 a[4], const u32 b[2]) {
    asm volatile("mma.sync.aligned.m16n8k16.row.col.f32.f16.f16.f32 "
                 "{%0,%1,%2,%3}, {%4,%5,%6,%7}, {%8,%9}, {%0,%1,%2,%3};"
                 : "+f"(c[0]), "+f"(c[1]), "+f"(c[2]), "+f"(c[3])
                 : "r"(a[0]), "r"(a[1]), "r"(a[2]), "r"(a[3]), "r"(b[0]), "r"(b[1]));
}
__device__ __forceinline__ void ldsm4(u32 r[4], u32 addr) {
    asm volatile("ldmatrix.sync.aligned.m8n8.x4.shared.b16 {%0,%1,%2,%3}, [%4];"
                 : "=r"(r[0]), "=r"(r[1]), "=r"(r[2]), "=r"(r[3]) : "r"(addr));
}
__device__ __forceinline__ u32 relu_cvt(float a, float b) {
    return cvt_f16x2(fmaxf(a, 0.0f), fmaxf(b, 0.0f));
}

__global__ void __launch_bounds__(TPB, 3)
bsde_kernel(const float* __restrict__ y0v, const float* __restrict__ Y0v,
            const float* __restrict__ qW1, const float* __restrict__ qb1,
            const float* __restrict__ qW2, const float* __restrict__ qb2,
            const float* __restrict__ qW3, const float* __restrict__ qb3,
            const float* __restrict__ zW1, const float* __restrict__ zb1,
            const float* __restrict__ zW2, const float* __restrict__ zb2,
            const float* __restrict__ zW3, const float* __restrict__ zb3,
            const float* __restrict__ dW, float* __restrict__ out) {
    __shared__ __align__(16) char sX[128 * 32];   // [row][16 f16]: 0-3 x_hi, 4-7 x_lo, 8 = 1.0, 9-15 = 0
    __shared__ __align__(16) float sP[128 * 4];   // [row]{z0,z1,z2,q}
    __shared__ float s_red[4];
    __shared__ int s_last;

    const int tid  = threadIdx.x;
    const int lane = tid & 31;
    const int wid  = tid >> 5;
    const int g    = lane >> 2;
    const int tg   = lane & 3;
    const int trunk = wid >> 1;   // 0 = z, 1 = q
    const int nsub  = wid & 1;    // m-half: m-tiles nsub*4 .. nsub*4+3

    const float* W1 = trunk ? qW1 : zW1;
    const float* B1 = trunk ? qb1 : zb1;
    const float* W2 = trunk ? qW2 : zW2;
    const float* B2 = trunk ? qb2 : zb2;

    // ---- B1 fragments: [16 k x 8 n] per nt. k 0-3 = W1 rows (x_hi), k 4-7 = W1 rows again (x_lo),
    //      k 8 = b1 (pairs with constant 1.0 in X), k 9-15 = 0 ----
    u32 B1f[16];
    #pragma unroll
    for (int nt = 0; nt < 8; nt++) {
        int n = nt * 8 + g;
        int ka = tg * 2, kb = tg * 2 + 1;       // 0..7
        float w0 = W1[(ka & 3) * 64 + n];
        float w1 = W1[(kb & 3) * 64 + n];
        B1f[nt * 2] = cvt_f16x2(w0, w1);
        float u0 = (tg == 0) ? B1[n] : 0.0f;    // k=8 row only
        B1f[nt * 2 + 1] = cvt_f16x2(u0, 0.0f);
    }

    // ---- B2 fragments: full N=64 for this trunk ----
    u32 B2f[64];
    #pragma unroll
    for (int nt = 0; nt < 8; nt++) {
        int n = nt * 8 + g;
        #pragma unroll
        for (int kt = 0; kt < 4; kt++) {
            #pragma unroll
            for (int r = 0; r < 2; r++) {
                int k0 = kt * 16 + tg * 2 + r * 8;
                B2f[nt * 8 + kt * 2 + r] = cvt_f16x2(W2[k0 * 64 + n], W2[(k0 + 1) * 64 + n]);
            }
        }
    }

    // ---- B3 fragments: K=64, n = 3 (z) or 1 (q), zero-padded to 8 ----
    u32 B3f[8];
    #pragma unroll
    for (int kt = 0; kt < 4; kt++) {
        #pragma unroll
        for (int r = 0; r < 2; r++) {
            int kb = kt * 16 + tg * 2 + r * 8;
            float w0 = 0.f, w1 = 0.f;
            if (trunk == 0) {
                if (g < 3) { w0 = zW3[kb * 3 + g]; w1 = zW3[(kb + 1) * 3 + g]; }
            } else {
                if (g == 0) { w0 = qW3[kb]; w1 = qW3[kb + 1]; }
            }
            B3f[kt * 2 + r] = cvt_f16x2(w0, w1);
        }
    }

    // ---- b2 accumulator-init values ----
    float b2c[16];
    #pragma unroll
    for (int nt = 0; nt < 8; nt++) {
        b2c[nt * 2]     = B2[nt * 8 + tg * 2];
        b2c[nt * 2 + 1] = B2[nt * 8 + tg * 2 + 1];
    }

    // ---- static X cols 8-15: {1.0, 0 x7} ----
    *(uint4*)(sX + tid * 32 + 16) = make_uint4(0x00003C00u, 0u, 0u, 0u);

    // ---- ldmatrix lane address for X a-frags ----
    const int mat = lane >> 3, r8 = lane & 7;
    const u32 xb = smem_u32(sX);
    const u32 xoff = xb + (u32)(((mat & 1) * 8 + r8) * 32 + (mat >> 1) * 16);

    const float zb3_0 = zb3[0], zb3_1 = zb3[1], zb3_2 = zb3[2], qb3_0 = qb3[0];
    const int gp = blockIdx.x * TPB + tid;
    const float dt = 0.02f;
    const float sqdt = sqrtf(dt);
    float y0 = y0v[0], y1 = y0v[1], y2 = y0v[2];
    float Y  = Y0v[0];
    __syncthreads();

    for (int n = 0; n < NSTEPS; n++) {
        const float* dwp = dW + ((size_t)n * BATCH + gp) * 3;
        float dw0 = dwp[0] * sqdt;
        float dw1 = dwp[1] * sqdt;
        float dw2 = dwp[2] * sqdt;
        float t = (float)n * dt;

        // ---- store x hi/lo (exact fp32 via residual split) ----
        {
            u32 h01 = cvt_f16x2(t,  y0);
            u32 h23 = cvt_f16x2(y1, y2);
            float2 f01 = __half22float2(*reinterpret_cast<__half2*>(&h01));
            float2 f23 = __half22float2(*reinterpret_cast<__half2*>(&h23));
            u32 l01 = cvt_f16x2(t  - f01.x, y0 - f01.y);
            u32 l23 = cvt_f16x2(y1 - f23.x, y2 - f23.y);
            *(uint4*)(sX + tid * 32) = make_uint4(h01, h23, l01, l23);
        }
        __syncthreads();   // X ready (also orders prev-step sP reads before new writes)

        // ---- this warp: 4 m-tiles, full 3-layer pipeline on tensor pipe ----
        #pragma unroll 1
        for (int mt = 0; mt < 4; mt++) {
            const int mrow = (nsub * 4 + mt) * 16;
            u32 ax[4];
            ldsm4(ax, xoff + (u32)(mrow * 32));

            // layer 1: h1[16x64] = X * W1ext  (bias via k=8 row)
            float c1[8][4];
            #pragma unroll
            for (int nt = 0; nt < 8; nt++) {
                c1[nt][0] = 0.f; c1[nt][1] = 0.f; c1[nt][2] = 0.f; c1[nt][3] = 0.f;
                mma16816(c1[nt], ax, &B1f[nt * 2]);
            }
            // relu + cvt -> layer-2 A fragments
            u32 a2[16];
            #pragma unroll
            for (int kt = 0; kt < 4; kt++) {
                a2[kt * 4 + 0] = relu_cvt(c1[2*kt][0],   c1[2*kt][1]);
                a2[kt * 4 + 1] = relu_cvt(c1[2*kt][2],   c1[2*kt][3]);
                a2[kt * 4 + 2] = relu_cvt(c1[2*kt+1][0], c1[2*kt+1][1]);
                a2[kt * 4 + 3] = relu_cvt(c1[2*kt+1][2], c1[2*kt+1][3]);
            }
            // layer 2 (accumulators init with b2)
            float c2[8][4];
            #pragma unroll
            for (int nt = 0; nt < 8; nt++) {
                c2[nt][0] = b2c[2*nt]; c2[nt][1] = b2c[2*nt+1];
                c2[nt][2] = b2c[2*nt]; c2[nt][3] = b2c[2*nt+1];
            }
            #pragma unroll
            for (int kt = 0; kt < 4; kt++) {
                #pragma unroll
                for (int nt = 0; nt < 8; nt++)
                    mma16816(c2[nt], &a2[kt * 4], &B2f[nt * 8 + kt * 2]);
            }
            // relu + cvt -> layer-3 A fragments
            u32 a3[16];
            #pragma unroll
            for (int kt = 0; kt < 4; kt++) {
                a3[kt * 4 + 0] = relu_cvt(c2[2*kt][0],   c2[2*kt][1]);
                a3[kt * 4 + 1] = relu_cvt(c2[2*kt][2],   c2[2*kt][3]);
                a3[kt * 4 + 2] = relu_cvt(c2[2*kt+1][0], c2[2*kt+1][1]);
                a3[kt * 4 + 3] = relu_cvt(c2[2*kt+1][2], c2[2*kt+1][3]);
            }
            // layer 3: full K=64 in-warp -> direct z/q
            float c3[4] = {0.f, 0.f, 0.f, 0.f};
            #pragma unroll
            for (int kt = 0; kt < 4; kt++)
                mma16816(c3, &a3[kt * 4], &B3f[kt * 2]);

            // scatter: rows mrow+g, mrow+g+8 ; c3 cols = {tg*2, tg*2+1}
            int row = mrow + g;
            if (trunk == 0) {
                if (tg == 0) {        // cols 0,1 -> z0,z1
                    *(float2*)&sP[row * 4]       = make_float2(c3[0], c3[1]);
                    *(float2*)&sP[(row + 8) * 4] = make_float2(c3[2], c3[3]);
                } else if (tg == 1) { // col 2 -> z2
                    sP[row * 4 + 2]       = c3[0];
                    sP[(row + 8) * 4 + 2] = c3[2];
                }
            } else {
                if (tg == 0) {        // col 0 -> q
                    sP[row * 4 + 3]       = c3[0];
                    sP[(row + 8) * 4 + 3] = c3[2];
                }
            }
        }
        __syncthreads();   // P ready

        // ---- gather, SDE update ----
        float4 pv = *(const float4*)&sP[tid * 4];
        float z0 = zb3_0 + pv.x;
        float z1 = zb3_1 + pv.y;
        float z2 = zb3_2 + pv.z;
        float q  = qb3_0 + pv.w;

        float f  = 0.5f * q * q;
        float s0 = 0.2f + 0.1f * tanhf(y0);
        float s1 = 0.2f + 0.1f * tanhf(y1);
        float s2 = 0.2f + 0.1f * tanhf(y2);
        y0 += (q - y0) * dt + s0 * dw0;
        y1 += (q - y1) * dt + s1 * dw1;
        y2 += (q - y2) * dt + s2 * dw2;
        Y  += -f * dt + z0 * dw0 + z1 * dw1 + z2 * dw2;
        // next iteration's X barrier orders sP reads before next scatter
    }

    // ---- per-path loss + deterministic reduction ----
    float term = y0 * y0 + y1 * y1 + y2 * y2;
    float v = Y - term;
    v = v * v;
    #pragma unroll
    for (int off = 16; off > 0; off >>= 1)
        v += __shfl_down_sync(0xffffffffu, v, off);
    if ((tid & 31) == 0) s_red[wid] = v;
    __syncthreads();
    if (tid == 0) {
        g_part[blockIdx.x] = s_red[0] + s_red[1] + s_red[2] + s_red[3];
        __threadfence();
        int c = atomicAdd(&g_cnt, 1);
        s_last = (c == NBLK - 1);
    }
    __syncthreads();
    if (s_last) {
        __threadfence();
        float acc = 0.0f;
        for (int i = tid; i < NBLK; i += TPB) acc += g_part[i];
        #pragma unroll
        for (int off = 16; off > 0; off >>= 1)
            acc += __shfl_down_sync(0xffffffffu, acc, off);
        if ((tid & 31) == 0) s_red[wid] = acc;
        __syncthreads();
        if (tid == 0) {
            out[0] = (s_red[0] + s_red[1] + s_red[2] + s_red[3]) * (1.0f / (float)BATCH);
            g_cnt = 0;   // reset for next replay
        }
    }
}

extern "C" void kernel_launch(void* const* d_in, const int* in_sizes, int n_in,
                              void* d_out, int out_size) {
    const float* y0  = (const float*)d_in[0];
    const float* Y0  = (const float*)d_in[1];
    const float* qW1 = (const float*)d_in[2];
    const float* qb1 = (const float*)d_in[3];
    const float* qW2 = (const float*)d_in[4];
    const float* qb2 = (const float*)d_in[5];
    const float* qW3 = (const float*)d_in[6];
    const float* qb3 = (const float*)d_in[7];
    const float* zW1 = (const float*)d_in[8];
    const float* zb1 = (const float*)d_in[9];
    const float* zW2 = (const float*)d_in[10];
    const float* zb2 = (const float*)d_in[11];
    const float* zW3 = (const float*)d_in[12];
    const float* zb3 = (const float*)d_in[13];
    const float* dW  = (const float*)d_in[14];

    bsde_kernel<<<NBLK, TPB>>>(y0, Y0, qW1, qb1, qW2, qb2, qW3, qb3,
                               zW1, zb1, zW2, zb2, zW3, zb3, dW, (float*)d_out);
}